// round 2
// baseline (speedup 1.0000x reference)
#include <cuda_runtime.h>
#include <math.h>

#define N_NODES 50000
#define N_EDGES 600000
#define HEADS 8
#define HID 128      // layer0 output width (8*16)
#define W1OUT 512    // layer1 gemm width (8*64)
#define NCLS 64

// ---------------- scratch (device globals; no allocation allowed) ----------------
__device__ float g_h0[(size_t)N_NODES * HID];      // x @ W0
__device__ float g_h1[(size_t)N_NODES * W1OUT];    // act @ W1
__device__ float g_as[N_NODES * HEADS];            // alpha_src per node/head
__device__ float g_ad[N_NODES * HEADS];            // alpha_dst per node/head
__device__ float g_m[N_NODES * HEADS];             // segment max
__device__ float g_den[N_NODES * HEADS];           // segment sum of exp
__device__ float g_e[(size_t)N_EDGES * HEADS];     // per-edge e, then ex
__device__ float g_agg0[(size_t)N_NODES * HID];    // layer0 aggregation
__device__ float g_acc[(size_t)N_NODES * NCLS];    // layer1 head-mean accumulator
__device__ int   g_is64;                           // edge_index dtype flag

// ---------------- dtype probe: int64 edge_index has zero high words ----------------
__global__ void detect_kernel(const int* __restrict__ ei_raw) {
    int allz = 1;
#pragma unroll
    for (int i = 1; i < 64; i += 2)
        if (ei_raw[i] != 0) { allz = 0; break; }
    g_is64 = allz;
}

__device__ __forceinline__ int edge_src(const void* ei, int e) {
    if (g_is64) return (int)((const long long*)ei)[e];
    return ((const int*)ei)[e];
}
__device__ __forceinline__ int edge_dst(const void* ei, int e) {
    if (g_is64) return (int)((const long long*)ei)[N_EDGES + e];
    return ((const int*)ei)[N_EDGES + e];
}

// ---------------- helpers ----------------
__device__ __forceinline__ void atomicMaxF(float* addr, float v) {
    int iv = __float_as_int(v);
    if (iv == (int)0x80000000) iv = 0;  // canonicalize -0 -> +0
    if (iv >= 0) atomicMax((int*)addr, iv);
    else atomicMin((unsigned int*)addr, (unsigned int)iv);
}

// ---------------- SGEMM: C[M,N] = A[M,K] @ B[K,N] ----------------
template <int BM, int BN, int BK, int TM, int TN>
__global__ void sgemm_kernel(int M, int N, int K,
                             const float* __restrict__ A,
                             const float* __restrict__ B,
                             float* __restrict__ C) {
    constexpr int THREADS = (BM / TM) * (BN / TN);
    __shared__ float As[BK][BM + 4];
    __shared__ float Bs[BK][BN];

    const int tid = threadIdx.x;
    const int row0 = blockIdx.y * BM;
    const int col0 = blockIdx.x * BN;
    const int trow = (tid / (BN / TN)) * TM;
    const int tcol = (tid % (BN / TN)) * TN;

    float acc[TM][TN];
#pragma unroll
    for (int i = 0; i < TM; i++)
#pragma unroll
        for (int j = 0; j < TN; j++) acc[i][j] = 0.f;

    for (int k0 = 0; k0 < K; k0 += BK) {
#pragma unroll
        for (int t = tid; t < BM * BK; t += THREADS) {
            int m = t / BK, k = t % BK;
            int gr = row0 + m;
            As[k][m] = (gr < M) ? A[(size_t)gr * K + k0 + k] : 0.f;
        }
#pragma unroll
        for (int t = tid; t < BK * BN; t += THREADS) {
            int k = t / BN, n = t % BN;
            Bs[k][n] = B[(size_t)(k0 + k) * N + col0 + n];
        }
        __syncthreads();

#pragma unroll
        for (int k = 0; k < BK; k++) {
            float rm[TM], rn[TN];
#pragma unroll
            for (int i = 0; i < TM; i++) rm[i] = As[k][trow + i];
#pragma unroll
            for (int j = 0; j < TN; j++) rn[j] = Bs[k][tcol + j];
#pragma unroll
            for (int i = 0; i < TM; i++)
#pragma unroll
                for (int j = 0; j < TN; j++) acc[i][j] += rm[i] * rn[j];
        }
        __syncthreads();
    }

#pragma unroll
    for (int i = 0; i < TM; i++) {
        int gr = row0 + trow + i;
        if (gr < M) {
#pragma unroll
            for (int j = 0; j < TN; j++)
                C[(size_t)gr * N + col0 + tcol + j] = acc[i][j];
        }
    }
}

// ---------------- alpha_s / alpha_d per (node, head): one warp each ----------------
__global__ void alpha_kernel(const float* __restrict__ h,
                             const float* __restrict__ av_s,
                             const float* __restrict__ av_d,
                             float* __restrict__ os, float* __restrict__ od,
                             int D) {
    int t = blockIdx.x * blockDim.x + threadIdx.x;
    int w = t >> 5, lane = t & 31;
    if (w >= N_NODES * HEADS) return;
    int n = w >> 3, hh = w & 7;
    const float* hp = h + (size_t)n * HEADS * D + hh * D;
    const float* sv = av_s + hh * D;
    const float* dv = av_d + hh * D;
    float ss = 0.f, sd = 0.f;
    for (int d = lane; d < D; d += 32) {
        float v = hp[d];
        ss += v * sv[d];
        sd += v * dv[d];
    }
#pragma unroll
    for (int o = 16; o; o >>= 1) {
        ss += __shfl_xor_sync(0xffffffffu, ss, o);
        sd += __shfl_xor_sync(0xffffffffu, sd, o);
    }
    if (lane == 0) { os[w] = ss; od[w] = sd; }
}

// ---------------- per-layer init: m=-inf, den=0, agg=0 ----------------
__global__ void init_kernel(float* __restrict__ m, float* __restrict__ den,
                            float* __restrict__ agg, int nagg) {
    int stride = gridDim.x * blockDim.x;
    int start = blockIdx.x * blockDim.x + threadIdx.x;
    for (int i = start; i < N_NODES * HEADS; i += stride) {
        m[i] = -INFINITY;
        den[i] = 0.f;
    }
    for (int i = start; i < nagg; i += stride) agg[i] = 0.f;
}

// ---------------- edge pass 1: e = leaky(as[src]+ad[dst]); store; atomicMax m[dst] ----------------
__global__ void edge_max_kernel(const void* __restrict__ ei,
                                const float* __restrict__ as,
                                const float* __restrict__ ad,
                                float* __restrict__ eout, float* __restrict__ m) {
    int e = blockIdx.x * blockDim.x + threadIdx.x;
    if (e >= N_EDGES) return;
    int src = edge_src(ei, e);
    int dst = edge_dst(ei, e);
    float4 s0 = ((const float4*)(as + src * 8))[0];
    float4 s1 = ((const float4*)(as + src * 8))[1];
    float4 d0 = ((const float4*)(ad + dst * 8))[0];
    float4 d1 = ((const float4*)(ad + dst * 8))[1];
    float v[8] = {s0.x + d0.x, s0.y + d0.y, s0.z + d0.z, s0.w + d0.w,
                  s1.x + d1.x, s1.y + d1.y, s1.z + d1.z, s1.w + d1.w};
#pragma unroll
    for (int h = 0; h < 8; h++) {
        float t = v[h];
        v[h] = t > 0.f ? t : 0.2f * t;
    }
    ((float4*)(eout + (size_t)e * 8))[0] = make_float4(v[0], v[1], v[2], v[3]);
    ((float4*)(eout + (size_t)e * 8))[1] = make_float4(v[4], v[5], v[6], v[7]);
#pragma unroll
    for (int h = 0; h < 8; h++) atomicMaxF(&m[dst * 8 + h], v[h]);
}

// ---------------- edge pass 2: ex = exp(e - m[dst]); store; atomicAdd den[dst] ----------------
__global__ void edge_exp_kernel(const void* __restrict__ ei,
                                float* __restrict__ ebuf,
                                const float* __restrict__ m, float* __restrict__ den) {
    int e = blockIdx.x * blockDim.x + threadIdx.x;
    if (e >= N_EDGES) return;
    int dst = edge_dst(ei, e);
    float4 e0 = ((const float4*)(ebuf + (size_t)e * 8))[0];
    float4 e1 = ((const float4*)(ebuf + (size_t)e * 8))[1];
    float4 m0 = ((const float4*)(m + dst * 8))[0];
    float4 m1 = ((const float4*)(m + dst * 8))[1];
    float v[8] = {expf(e0.x - m0.x), expf(e0.y - m0.y), expf(e0.z - m0.z), expf(e0.w - m0.w),
                  expf(e1.x - m1.x), expf(e1.y - m1.y), expf(e1.z - m1.z), expf(e1.w - m1.w)};
    ((float4*)(ebuf + (size_t)e * 8))[0] = make_float4(v[0], v[1], v[2], v[3]);
    ((float4*)(ebuf + (size_t)e * 8))[1] = make_float4(v[4], v[5], v[6], v[7]);
#pragma unroll
    for (int h = 0; h < 8; h++) atomicAdd(&den[dst * 8 + h], v[h]);
}

// ---------------- layer0 scatter: agg0[dst, h*16+d] += alpha * h0[src, h*16+d] ----------------
__global__ void scatter0_kernel(const void* __restrict__ ei,
                                const float* __restrict__ ex,
                                const float* __restrict__ den,
                                const float* __restrict__ h,
                                float* __restrict__ agg) {
    int gid = blockIdx.x * blockDim.x + threadIdx.x;
    if (gid >= N_EDGES * HID) return;
    int e = gid >> 7;          // /128
    int idx = gid & 127;
    int hh = idx >> 4;         // /16
    int src = edge_src(ei, e);
    int dst = edge_dst(ei, e);
    float a = ex[(size_t)e * 8 + hh] / (den[dst * 8 + hh] + 1e-16f);
    atomicAdd(&agg[(size_t)dst * HID + idx], a * h[(size_t)src * HID + idx]);
}

// ---------------- elu(agg0 + b0) in place ----------------
__global__ void elu_kernel(float* __restrict__ a, const float* __restrict__ b) {
    int i = blockIdx.x * blockDim.x + threadIdx.x;
    if (i >= N_NODES * HID) return;
    float v = a[i] + b[i & 127];
    a[i] = v > 0.f ? v : expm1f(v);
}

// ---------------- layer1 scatter fused with head-mean ----------------
__global__ void scatter1_kernel(const void* __restrict__ ei,
                                const float* __restrict__ ex,
                                const float* __restrict__ den,
                                const float* __restrict__ h,
                                float* __restrict__ acc) {
    int gid = blockIdx.x * blockDim.x + threadIdx.x;
    if (gid >= N_EDGES * NCLS) return;
    int e = gid >> 6;  // /64
    int c = gid & 63;
    int src = edge_src(ei, e);
    int dst = edge_dst(ei, e);
    const float* hrow = h + (size_t)src * W1OUT + c;
    float s = 0.f;
#pragma unroll
    for (int hh = 0; hh < 8; hh++) {
        float a = ex[(size_t)e * 8 + hh] / (den[dst * 8 + hh] + 1e-16f);
        s += a * hrow[hh * 64];
    }
    atomicAdd(&acc[(size_t)dst * NCLS + c], s);
}

// ---------------- finalize: out = log_softmax(acc/8 + b1); one warp per node ----------------
__global__ void finalize_kernel(const float* __restrict__ acc,
                                const float* __restrict__ b1,
                                float* __restrict__ out) {
    int t = blockIdx.x * blockDim.x + threadIdx.x;
    int n = t >> 5, lane = t & 31;
    if (n >= N_NODES) return;
    float v0 = acc[(size_t)n * NCLS + lane] * 0.125f + b1[lane];
    float v1 = acc[(size_t)n * NCLS + lane + 32] * 0.125f + b1[lane + 32];
    float mx = fmaxf(v0, v1);
#pragma unroll
    for (int o = 16; o; o >>= 1) mx = fmaxf(mx, __shfl_xor_sync(0xffffffffu, mx, o));
    float s = expf(v0 - mx) + expf(v1 - mx);
#pragma unroll
    for (int o = 16; o; o >>= 1) s += __shfl_xor_sync(0xffffffffu, s, o);
    float lse = mx + logf(s);
    out[(size_t)n * NCLS + lane] = v0 - lse;
    out[(size_t)n * NCLS + lane + 32] = v1 - lse;
}

// ---------------- launch ----------------
extern "C" void kernel_launch(void* const* d_in, const int* in_sizes, int n_in,
                              void* d_out, int out_size) {
    const float* x   = (const float*)d_in[0];
    const void*  ei  = d_in[1];
    const float* W0  = (const float*)d_in[2];
    const float* as0 = (const float*)d_in[3];
    const float* ad0 = (const float*)d_in[4];
    const float* b0  = (const float*)d_in[5];
    const float* W1  = (const float*)d_in[6];
    const float* as1 = (const float*)d_in[7];
    const float* ad1 = (const float*)d_in[8];
    const float* b1  = (const float*)d_in[9];
    float* out = (float*)d_out;

    float *h0, *h1, *as, *ad, *m, *den, *eb, *agg0, *acc;
    cudaGetSymbolAddress((void**)&h0,   g_h0);
    cudaGetSymbolAddress((void**)&h1,   g_h1);
    cudaGetSymbolAddress((void**)&as,   g_as);
    cudaGetSymbolAddress((void**)&ad,   g_ad);
    cudaGetSymbolAddress((void**)&m,    g_m);
    cudaGetSymbolAddress((void**)&den,  g_den);
    cudaGetSymbolAddress((void**)&eb,   g_e);
    cudaGetSymbolAddress((void**)&agg0, g_agg0);
    cudaGetSymbolAddress((void**)&acc,  g_acc);

    const int TB = 256;
    dim3 blk(TB);

    detect_kernel<<<1, 1>>>((const int*)ei);

    // ======== layer 0 ========
    {
        dim3 grid(HID / 128, (N_NODES + 127) / 128);
        sgemm_kernel<128, 128, 16, 8, 8><<<grid, 256>>>(N_NODES, HID, 256, x, W0, h0);
    }
    alpha_kernel<<<(N_NODES * HEADS * 32 + TB - 1) / TB, blk>>>(h0, as0, ad0, as, ad, 16);
    init_kernel<<<4096, blk>>>(m, den, agg0, N_NODES * HID);
    edge_max_kernel<<<(N_EDGES + TB - 1) / TB, blk>>>(ei, as, ad, eb, m);
    edge_exp_kernel<<<(N_EDGES + TB - 1) / TB, blk>>>(ei, eb, m, den);
    scatter0_kernel<<<(N_EDGES * HID + TB - 1) / TB, blk>>>(ei, eb, den, h0, agg0);
    elu_kernel<<<(N_NODES * HID + TB - 1) / TB, blk>>>(agg0, b0);

    // ======== layer 1 ========
    {
        dim3 grid(W1OUT / 128, (N_NODES + 127) / 128);
        sgemm_kernel<128, 128, 16, 8, 8><<<grid, 256>>>(N_NODES, W1OUT, HID, agg0, W1, h1);
    }
    alpha_kernel<<<(N_NODES * HEADS * 32 + TB - 1) / TB, blk>>>(h1, as1, ad1, as, ad, 64);
    init_kernel<<<4096, blk>>>(m, den, acc, N_NODES * NCLS);
    edge_max_kernel<<<(N_EDGES + TB - 1) / TB, blk>>>(ei, as, ad, eb, m);
    edge_exp_kernel<<<(N_EDGES + TB - 1) / TB, blk>>>(ei, eb, m, den);
    scatter1_kernel<<<(N_EDGES * NCLS + TB - 1) / TB, blk>>>(ei, eb, den, h1, acc);
    finalize_kernel<<<(N_NODES * 32 + TB - 1) / TB, blk>>>(acc, b1, out);
}

// round 3
// speedup vs baseline: 2.4664x; 2.4664x over previous
#include <cuda_runtime.h>
#include <math.h>

#define N_NODES 50000
#define N_EDGES 600000
#define HEADS 8
#define HID 128      // layer0 output width (8*16)
#define W1OUT 512    // layer1 gemm width (8*64)
#define NCLS 64

// ---------------- scratch (device globals) ----------------
__device__ float g_h0[(size_t)N_NODES * HID];       // x @ W0
__device__ float g_h1[(size_t)N_NODES * W1OUT];     // act @ W1p (head-interleaved: [n][c*8+h])
__device__ float g_as[N_NODES * HEADS];
__device__ float g_ad[N_NODES * HEADS];
__device__ float g_den[N_NODES * HEADS];
__device__ float g_alpha[(size_t)N_EDGES * HEADS];  // exp(e) per edge/head
__device__ float g_agg0[(size_t)N_NODES * HID];     // layer0 output (post-ELU)
__device__ float g_W1p[HID * W1OUT];                // W1 with permuted columns
__device__ int   g_deg[N_NODES];
__device__ int   g_cur[N_NODES];
__device__ int   g_rowptr[N_NODES + 1];
__device__ int   g_csr_src[N_EDGES];
__device__ int   g_csr_eid[N_EDGES];
__device__ int   g_is64;

// ---------------- dtype probe: int64 edge_index has zero high words ----------------
__global__ void detect_kernel(const int* __restrict__ ei_raw) {
    int allz = 1;
#pragma unroll
    for (int i = 1; i < 64; i += 2)
        if (ei_raw[i] != 0) { allz = 0; break; }
    g_is64 = allz;
}
__device__ __forceinline__ int edge_src(const void* ei, int e) {
    if (g_is64) return (int)((const long long*)ei)[e];
    return ((const int*)ei)[e];
}
__device__ __forceinline__ int edge_dst(const void* ei, int e) {
    if (g_is64) return (int)((const long long*)ei)[N_EDGES + e];
    return ((const int*)ei)[N_EDGES + e];
}

// ---------------- CSR build ----------------
__global__ void zero_csr_kernel(int* __restrict__ a, int* __restrict__ b) {
    int i = blockIdx.x * blockDim.x + threadIdx.x;
    if (i < N_NODES) { a[i] = 0; b[i] = 0; }
}
__global__ void zero_den_kernel(float* __restrict__ d) {
    int i = blockIdx.x * blockDim.x + threadIdx.x;
    if (i < N_NODES * HEADS) d[i] = 0.f;
}
__global__ void hist_kernel(const void* __restrict__ ei, int* __restrict__ deg) {
    int e = blockIdx.x * blockDim.x + threadIdx.x;
    if (e >= N_EDGES) return;
    atomicAdd(&deg[edge_dst(ei, e)], 1);
}
// single-block exclusive scan over N_NODES (warp scans + carry)
__global__ void scan_kernel(const int* __restrict__ deg, int* __restrict__ row_ptr) {
    __shared__ int wsum[32];
    __shared__ int s_carry;
    int tid = threadIdx.x, lane = tid & 31, wid = tid >> 5;
    if (tid == 0) s_carry = 0;
    __syncthreads();
    for (int base = 0; base < N_NODES; base += 1024) {
        int i = base + tid;
        int v = (i < N_NODES) ? deg[i] : 0;
        int x = v;
#pragma unroll
        for (int off = 1; off < 32; off <<= 1) {
            int t = __shfl_up_sync(0xffffffffu, x, off);
            if (lane >= off) x += t;
        }
        if (lane == 31) wsum[wid] = x;
        __syncthreads();
        if (wid == 0) {
            int y = wsum[lane];
#pragma unroll
            for (int off = 1; off < 32; off <<= 1) {
                int t = __shfl_up_sync(0xffffffffu, y, off);
                if (lane >= off) y += t;
            }
            wsum[lane] = y;
        }
        __syncthreads();
        int woff = (wid > 0) ? wsum[wid - 1] : 0;
        if (i < N_NODES) row_ptr[i] = s_carry + woff + x - v;
        __syncthreads();
        if (tid == 0) s_carry += wsum[31];
        __syncthreads();
    }
    if (threadIdx.x == 0) row_ptr[N_NODES] = s_carry;
}
__global__ void fill_kernel(const void* __restrict__ ei, const int* __restrict__ row_ptr,
                            int* __restrict__ cur, int* __restrict__ csr_src,
                            int* __restrict__ csr_eid) {
    int e = blockIdx.x * blockDim.x + threadIdx.x;
    if (e >= N_EDGES) return;
    int dst = edge_dst(ei, e);
    int src = edge_src(ei, e);
    int p = row_ptr[dst] + atomicAdd(&cur[dst], 1);
    csr_src[p] = src;
    csr_eid[p] = e;
}

// ---------------- SGEMM (float4 loads): C[M,N] = A[M,K] @ B[K,N] ----------------
template <int BM, int BN, int BK, int TM, int TN>
__global__ void sgemm_kernel(int M, int N, int K,
                             const float* __restrict__ A,
                             const float* __restrict__ B,
                             float* __restrict__ C) {
    __shared__ float As[BK][BM + 4];
    __shared__ float Bs[BK][BN];
    const int tid = threadIdx.x;
    const int row0 = blockIdx.y * BM;
    const int col0 = blockIdx.x * BN;
    const int ar = tid >> 2;          // 0..63
    const int ac = (tid & 3) * 4;     // 0,4,8,12
    const int br = tid >> 5;          // 0..7
    const int bc = (tid & 31) * 4;
    const int trow = (tid / (BN / TN)) * TM;
    const int tcol = (tid % (BN / TN)) * TN;

    float acc[TM][TN];
#pragma unroll
    for (int i = 0; i < TM; i++)
#pragma unroll
        for (int j = 0; j < TN; j++) acc[i][j] = 0.f;

    for (int k0 = 0; k0 < K; k0 += BK) {
#pragma unroll
        for (int rr = 0; rr < 2; rr++) {
            int m = ar + rr * 64;
            int gr = row0 + m;
            float4 av = (gr < M) ? *(const float4*)(A + (size_t)gr * K + k0 + ac)
                                 : make_float4(0.f, 0.f, 0.f, 0.f);
            As[ac + 0][m] = av.x; As[ac + 1][m] = av.y;
            As[ac + 2][m] = av.z; As[ac + 3][m] = av.w;
        }
#pragma unroll
        for (int rr = 0; rr < 2; rr++) {
            int k = br + rr * 8;
            *(float4*)&Bs[k][bc] = *(const float4*)(B + (size_t)(k0 + k) * N + col0 + bc);
        }
        __syncthreads();

#pragma unroll
        for (int k = 0; k < BK; k++) {
            float rm[TM], rn[TN];
#pragma unroll
            for (int i = 0; i < TM; i++) rm[i] = As[k][trow + i];
#pragma unroll
            for (int j = 0; j < TN; j++) rn[j] = Bs[k][tcol + j];
#pragma unroll
            for (int i = 0; i < TM; i++)
#pragma unroll
                for (int j = 0; j < TN; j++) acc[i][j] += rm[i] * rn[j];
        }
        __syncthreads();
    }

#pragma unroll
    for (int i = 0; i < TM; i++) {
        int gr = row0 + trow + i;
        if (gr < M) {
#pragma unroll
            for (int j4 = 0; j4 < TN / 4; j4++) {
                float4 v = make_float4(acc[i][j4 * 4], acc[i][j4 * 4 + 1],
                                       acc[i][j4 * 4 + 2], acc[i][j4 * 4 + 3]);
                *(float4*)(C + (size_t)gr * N + col0 + tcol + j4 * 4) = v;
            }
        }
    }
}

// ---------------- W1 column permutation: W1p[k][c*8+h] = W1[k][h*64+c] ----------------
__global__ void permW1_kernel(const float* __restrict__ W1, float* __restrict__ W1p) {
    int i = blockIdx.x * blockDim.x + threadIdx.x;
    if (i >= HID * W1OUT) return;
    int k = i >> 9;
    int j = i & 511;        // j = h*64+c
    int hh = j >> 6, c = j & 63;
    W1p[(size_t)k * W1OUT + c * 8 + hh] = W1[i];
}

// ---------------- alpha layer0: warp per node, h0 layout [n][h*16+d] ----------------
__global__ void alpha0_kernel(const float* __restrict__ h,
                              const float* __restrict__ av_s,
                              const float* __restrict__ av_d,
                              float* __restrict__ os, float* __restrict__ od) {
    int t = blockIdx.x * blockDim.x + threadIdx.x;
    int n = t >> 5, l = t & 31;
    if (n >= N_NODES) return;
    float4 hv = *(const float4*)(h + (size_t)n * HID + l * 4);
    int hh = l >> 2;
    float4 sa = *(const float4*)(av_s + hh * 16 + (l & 3) * 4);
    float4 da = *(const float4*)(av_d + hh * 16 + (l & 3) * 4);
    float ss = hv.x * sa.x + hv.y * sa.y + hv.z * sa.z + hv.w * sa.w;
    float sd = hv.x * da.x + hv.y * da.y + hv.z * da.z + hv.w * da.w;
    ss += __shfl_xor_sync(0xffffffffu, ss, 1);
    ss += __shfl_xor_sync(0xffffffffu, ss, 2);
    sd += __shfl_xor_sync(0xffffffffu, sd, 1);
    sd += __shfl_xor_sync(0xffffffffu, sd, 2);
    if ((l & 3) == 0) { os[n * 8 + hh] = ss; od[n * 8 + hh] = sd; }
}

// ---------------- alpha layer1: warp per node, h1p layout [n][c*8+h] ----------------
__global__ void alpha1_kernel(const float* __restrict__ h,
                              const float* __restrict__ av_s,
                              const float* __restrict__ av_d,
                              float* __restrict__ os, float* __restrict__ od) {
    int t = blockIdx.x * blockDim.x + threadIdx.x;
    int n = t >> 5, l = t & 31;
    if (n >= N_NODES) return;
    float ss[8], sd[8];
#pragma unroll
    for (int hh = 0; hh < 8; hh++) { ss[hh] = 0.f; sd[hh] = 0.f; }
#pragma unroll
    for (int cc = 0; cc < 2; cc++) {
        int c = l + cc * 32;
        const float4* hp = (const float4*)(h + (size_t)n * W1OUT + c * 8);
        float4 v0 = hp[0], v1 = hp[1];
        float va[8] = {v0.x, v0.y, v0.z, v0.w, v1.x, v1.y, v1.z, v1.w};
#pragma unroll
        for (int hh = 0; hh < 8; hh++) {
            ss[hh] += va[hh] * av_s[hh * 64 + c];
            sd[hh] += va[hh] * av_d[hh * 64 + c];
        }
    }
#pragma unroll
    for (int hh = 0; hh < 8; hh++) {
#pragma unroll
        for (int o = 16; o; o >>= 1) {
            ss[hh] += __shfl_xor_sync(0xffffffffu, ss[hh], o);
            sd[hh] += __shfl_xor_sync(0xffffffffu, sd[hh], o);
        }
    }
    if (l == 0) {
#pragma unroll
        for (int hh = 0; hh < 8; hh++) { os[n * 8 + hh] = ss[hh]; od[n * 8 + hh] = sd[hh]; }
    }
}

// ---------------- edge exp: alpha = exp(leaky(as[src]+ad[dst])); atomicAdd den ----------------
__global__ void edge_exp_kernel(const void* __restrict__ ei,
                                const float* __restrict__ as,
                                const float* __restrict__ ad,
                                float* __restrict__ alpha, float* __restrict__ den) {
    int e = blockIdx.x * blockDim.x + threadIdx.x;
    if (e >= N_EDGES) return;
    int src = edge_src(ei, e);
    int dst = edge_dst(ei, e);
    float4 s0 = ((const float4*)(as + src * 8))[0];
    float4 s1 = ((const float4*)(as + src * 8))[1];
    float4 d0 = ((const float4*)(ad + dst * 8))[0];
    float4 d1 = ((const float4*)(ad + dst * 8))[1];
    float v[8] = {s0.x + d0.x, s0.y + d0.y, s0.z + d0.z, s0.w + d0.w,
                  s1.x + d1.x, s1.y + d1.y, s1.z + d1.z, s1.w + d1.w};
#pragma unroll
    for (int h = 0; h < 8; h++) {
        float t = v[h];
        t = t > 0.f ? t : 0.2f * t;
        v[h] = expf(t);
    }
    ((float4*)(alpha + (size_t)e * 8))[0] = make_float4(v[0], v[1], v[2], v[3]);
    ((float4*)(alpha + (size_t)e * 8))[1] = make_float4(v[4], v[5], v[6], v[7]);
#pragma unroll
    for (int h = 0; h < 8; h++) atomicAdd(&den[dst * 8 + h], v[h]);
}

// ---------------- layer0 aggregation: block(128) per dst, fused bias+ELU ----------------
__global__ void agg0_kernel(const int* __restrict__ row_ptr,
                            const int* __restrict__ csr_src,
                            const int* __restrict__ csr_eid,
                            const float* __restrict__ alpha,
                            const float* __restrict__ den,
                            const float* __restrict__ h,
                            const float* __restrict__ b0,
                            float* __restrict__ out) {
    int dst = blockIdx.x;
    int idx = threadIdx.x;  // channel = hh*16+d
    __shared__ float rden[8];
    if (idx < 8) rden[idx] = 1.f / (den[dst * 8 + idx] + 1e-16f);
    __syncthreads();
    int s = row_ptr[dst], epos = row_ptr[dst + 1];
    int hh = idx >> 4;
    float r = rden[hh];
    float acc = 0.f;
    for (int p = s; p < epos; p++) {
        int src = csr_src[p];
        int eid = csr_eid[p];
        float a = alpha[(size_t)eid * 8 + hh] * r;
        acc += a * h[(size_t)src * HID + idx];
    }
    float v = acc + b0[idx];
    out[(size_t)dst * HID + idx] = v > 0.f ? v : expm1f(v);
}

// ---------------- layer1 aggregation: block(64) per dst, fused mean+bias+log_softmax ----------------
__global__ void agg1_kernel(const int* __restrict__ row_ptr,
                            const int* __restrict__ csr_src,
                            const int* __restrict__ csr_eid,
                            const float* __restrict__ alpha,
                            const float* __restrict__ den,
                            const float* __restrict__ h,   // [n][c*8+hh]
                            const float* __restrict__ b1,
                            float* __restrict__ out) {
    int dst = blockIdx.x;
    int c = threadIdx.x;  // 0..63
    __shared__ float rden[8];
    __shared__ float red_mx[2];
    __shared__ float red_sm[2];
    if (c < 8) rden[c] = 1.f / (den[dst * 8 + c] + 1e-16f);
    __syncthreads();
    float r0 = rden[0], r1 = rden[1], r2 = rden[2], r3 = rden[3];
    float r4 = rden[4], r5 = rden[5], r6 = rden[6], r7 = rden[7];
    int s = row_ptr[dst], epos = row_ptr[dst + 1];
    float acc = 0.f;
    for (int p = s; p < epos; p++) {
        int src = csr_src[p];
        int eid = csr_eid[p];
        float4 a0 = ((const float4*)(alpha + (size_t)eid * 8))[0];
        float4 a1 = ((const float4*)(alpha + (size_t)eid * 8))[1];
        const float4* hp = (const float4*)(h + (size_t)src * W1OUT + c * 8);
        float4 v0 = hp[0], v1 = hp[1];
        acc += (a0.x * r0) * v0.x + (a0.y * r1) * v0.y + (a0.z * r2) * v0.z + (a0.w * r3) * v0.w
             + (a1.x * r4) * v1.x + (a1.y * r5) * v1.y + (a1.z * r6) * v1.z + (a1.w * r7) * v1.w;
    }
    float v = acc * 0.125f + b1[c];
    // block (64) log_softmax
    float mx = v;
#pragma unroll
    for (int o = 16; o; o >>= 1) mx = fmaxf(mx, __shfl_xor_sync(0xffffffffu, mx, o));
    if ((c & 31) == 0) red_mx[c >> 5] = mx;
    __syncthreads();
    mx = fmaxf(red_mx[0], red_mx[1]);
    float ex = expf(v - mx);
    float sm = ex;
#pragma unroll
    for (int o = 16; o; o >>= 1) sm += __shfl_xor_sync(0xffffffffu, sm, o);
    if ((c & 31) == 0) red_sm[c >> 5] = sm;
    __syncthreads();
    float lse = mx + logf(red_sm[0] + red_sm[1]);
    out[(size_t)dst * NCLS + c] = v - lse;
}

// ---------------- launch ----------------
extern "C" void kernel_launch(void* const* d_in, const int* in_sizes, int n_in,
                              void* d_out, int out_size) {
    const float* x   = (const float*)d_in[0];
    const void*  ei  = d_in[1];
    const float* W0  = (const float*)d_in[2];
    const float* as0 = (const float*)d_in[3];
    const float* ad0 = (const float*)d_in[4];
    const float* b0  = (const float*)d_in[5];
    const float* W1  = (const float*)d_in[6];
    const float* as1 = (const float*)d_in[7];
    const float* ad1 = (const float*)d_in[8];
    const float* b1  = (const float*)d_in[9];
    float* out = (float*)d_out;

    float *h0, *h1, *as, *ad, *den, *alpha, *agg0, *W1p;
    int *deg, *cur, *rowptr, *csrs, *csre;
    cudaGetSymbolAddress((void**)&h0,    g_h0);
    cudaGetSymbolAddress((void**)&h1,    g_h1);
    cudaGetSymbolAddress((void**)&as,    g_as);
    cudaGetSymbolAddress((void**)&ad,    g_ad);
    cudaGetSymbolAddress((void**)&den,   g_den);
    cudaGetSymbolAddress((void**)&alpha, g_alpha);
    cudaGetSymbolAddress((void**)&agg0,  g_agg0);
    cudaGetSymbolAddress((void**)&W1p,   g_W1p);
    cudaGetSymbolAddress((void**)&deg,   g_deg);
    cudaGetSymbolAddress((void**)&cur,   g_cur);
    cudaGetSymbolAddress((void**)&rowptr,g_rowptr);
    cudaGetSymbolAddress((void**)&csrs,  g_csr_src);
    cudaGetSymbolAddress((void**)&csre,  g_csr_eid);

    const int TB = 256;
    const int EBLK = (N_EDGES + TB - 1) / TB;
    const int NBLK = (N_NODES + TB - 1) / TB;
    const int WBLK = (N_NODES * 32 + TB - 1) / TB;

    detect_kernel<<<1, 1>>>((const int*)ei);

    // CSR build (shared by both layers)
    zero_csr_kernel<<<NBLK, TB>>>(deg, cur);
    hist_kernel<<<EBLK, TB>>>(ei, deg);
    scan_kernel<<<1, 1024>>>(deg, rowptr);
    fill_kernel<<<EBLK, TB>>>(ei, rowptr, cur, csrs, csre);

    // ======== layer 0 ========
    sgemm_kernel<128, 128, 16, 8, 8><<<dim3(1, (N_NODES + 127) / 128), 256>>>(
        N_NODES, HID, 256, x, W0, h0);
    alpha0_kernel<<<WBLK, TB>>>(h0, as0, ad0, as, ad);
    zero_den_kernel<<<(N_NODES * 8 + TB - 1) / TB, TB>>>(den);
    edge_exp_kernel<<<EBLK, TB>>>(ei, as, ad, alpha, den);
    agg0_kernel<<<N_NODES, 128>>>(rowptr, csrs, csre, alpha, den, h0, b0, agg0);

    // ======== layer 1 ========
    permW1_kernel<<<(HID * W1OUT + TB - 1) / TB, TB>>>(W1, W1p);
    sgemm_kernel<128, 128, 16, 8, 8><<<dim3(W1OUT / 128, (N_NODES + 127) / 128), 256>>>(
        N_NODES, W1OUT, HID, agg0, W1p, h1);
    alpha1_kernel<<<WBLK, TB>>>(h1, as1, ad1, as, ad);
    zero_den_kernel<<<(N_NODES * 8 + TB - 1) / TB, TB>>>(den);
    edge_exp_kernel<<<EBLK, TB>>>(ei, as, ad, alpha, den);
    agg1_kernel<<<N_NODES, 64>>>(rowptr, csrs, csre, alpha, den, h1, b1, out);
}

// round 4
// speedup vs baseline: 2.6275x; 1.0653x over previous
#include <cuda_runtime.h>
#include <math.h>

#define N_NODES 50000
#define N_EDGES 600000
#define HEADS 8
#define HID 128
#define W1OUT 512
#define NCLS 64
#define SCAN_B 256
#define SCAN_G ((N_NODES + SCAN_B - 1) / SCAN_B)

// ---------------- scratch ----------------
__device__ float g_h0[(size_t)N_NODES * HID];
__device__ float g_h1[(size_t)N_NODES * W1OUT];    // [n][c*8+h] (permuted)
__device__ float g_as[N_NODES * HEADS];
__device__ float g_ad[N_NODES * HEADS];
__device__ float g_alpha[(size_t)N_EDGES * HEADS]; // CSR-position order
__device__ float g_agg0[(size_t)N_NODES * HID];
__device__ float g_W1p[HID * W1OUT];
__device__ int   g_deg[N_NODES];
__device__ int   g_cur[N_NODES];
__device__ int   g_rowptr[N_NODES + 1];
__device__ int   g_csr_src[N_EDGES];
__device__ int   g_csr_dst[N_EDGES];
__device__ int   g_bsum[SCAN_G];
__device__ int   g_boff[SCAN_G];
__device__ int   g_is64;

// ---------------- dtype probe ----------------
__global__ void detect_kernel(const int* __restrict__ ei_raw) {
    int allz = 1;
#pragma unroll
    for (int i = 1; i < 64; i += 2)
        if (ei_raw[i] != 0) { allz = 0; break; }
    g_is64 = allz;
}
__device__ __forceinline__ int edge_src(const void* ei, int e) {
    if (g_is64) return (int)((const long long*)ei)[e];
    return ((const int*)ei)[e];
}
__device__ __forceinline__ int edge_dst(const void* ei, int e) {
    if (g_is64) return (int)((const long long*)ei)[N_EDGES + e];
    return ((const int*)ei)[N_EDGES + e];
}

// ---------------- CSR build ----------------
__global__ void zero_csr_kernel(int* __restrict__ a, int* __restrict__ b) {
    int i = blockIdx.x * blockDim.x + threadIdx.x;
    if (i < N_NODES) { a[i] = 0; b[i] = 0; }
}
__global__ void hist_kernel(const void* __restrict__ ei, int* __restrict__ deg) {
    int e = blockIdx.x * blockDim.x + threadIdx.x;
    if (e >= N_EDGES) return;
    atomicAdd(&deg[edge_dst(ei, e)], 1);
}
// scan stage A: per-block sums
__global__ void scanA_kernel(const int* __restrict__ deg, int* __restrict__ bsum) {
    __shared__ int ws[8];
    int tid = threadIdx.x, lane = tid & 31, wid = tid >> 5;
    int i = blockIdx.x * SCAN_B + tid;
    int x = (i < N_NODES) ? deg[i] : 0;
#pragma unroll
    for (int o = 16; o; o >>= 1) x += __shfl_down_sync(0xffffffffu, x, o);
    if (lane == 0) ws[wid] = x;
    __syncthreads();
    if (tid == 0) {
        int t = 0;
#pragma unroll
        for (int j = 0; j < 8; j++) t += ws[j];
        bsum[blockIdx.x] = t;
    }
}
// scan stage B: exclusive scan of SCAN_G block sums (1 block of 256)
__global__ void scanB_kernel(const int* __restrict__ bsum, int* __restrict__ boff) {
    __shared__ int ws[8];
    int tid = threadIdx.x, lane = tid & 31, wid = tid >> 5;
    int v = (tid < SCAN_G) ? bsum[tid] : 0;
    int x = v;
#pragma unroll
    for (int o = 1; o < 32; o <<= 1) {
        int t = __shfl_up_sync(0xffffffffu, x, o);
        if (lane >= o) x += t;
    }
    if (lane == 31) ws[wid] = x;
    __syncthreads();
    if (tid == 0) {
        int run = 0;
#pragma unroll
        for (int j = 0; j < 8; j++) { int t = ws[j]; ws[j] = run; run += t; }
    }
    __syncthreads();
    if (tid < SCAN_G) boff[tid] = x - v + ws[wid];
}
// scan stage C: rescan each block + offset
__global__ void scanC_kernel(const int* __restrict__ deg, const int* __restrict__ boff,
                             int* __restrict__ row_ptr) {
    __shared__ int ws[8];
    int tid = threadIdx.x, lane = tid & 31, wid = tid >> 5;
    int i = blockIdx.x * SCAN_B + tid;
    int v = (i < N_NODES) ? deg[i] : 0;
    int x = v;
#pragma unroll
    for (int o = 1; o < 32; o <<= 1) {
        int t = __shfl_up_sync(0xffffffffu, x, o);
        if (lane >= o) x += t;
    }
    if (lane == 31) ws[wid] = x;
    __syncthreads();
    if (tid == 0) {
        int run = 0;
#pragma unroll
        for (int j = 0; j < 8; j++) { int t = ws[j]; ws[j] = run; run += t; }
    }
    __syncthreads();
    if (i < N_NODES) row_ptr[i] = x - v + ws[wid] + boff[blockIdx.x];
    if (blockIdx.x == 0 && tid == 0) row_ptr[N_NODES] = N_EDGES;
}
__global__ void fill_kernel(const void* __restrict__ ei, const int* __restrict__ row_ptr,
                            int* __restrict__ cur, int* __restrict__ csr_src,
                            int* __restrict__ csr_dst) {
    int e = blockIdx.x * blockDim.x + threadIdx.x;
    if (e >= N_EDGES) return;
    int dst = edge_dst(ei, e);
    int src = edge_src(ei, e);
    int p = row_ptr[dst] + atomicAdd(&cur[dst], 1);
    csr_src[p] = src;
    csr_dst[p] = dst;
}

// ---------------- double-buffered SGEMM: C[M,N] = A[M,K] @ B[K,N] ----------------
template <int BM, int BN, int BK, int TM, int TN>
__global__ void sgemm_kernel(int M, int N, int K,
                             const float* __restrict__ A,
                             const float* __restrict__ B,
                             float* __restrict__ C) {
    __shared__ float As[2][BK][BM + 4];
    __shared__ float Bs[2][BK][BN];
    const int tid = threadIdx.x;
    const int row0 = blockIdx.y * BM;
    const int col0 = blockIdx.x * BN;
    const int ar = tid >> 2;        // 0..63
    const int ac = (tid & 3) * 4;   // 0..12
    const int br = tid >> 5;        // 0..7
    const int bc = (tid & 31) * 4;
    const int trow = (tid / (BN / TN)) * TM;
    const int tcol = (tid % (BN / TN)) * TN;

    float4 pa0, pa1, pb0, pb1;
    float acc[TM][TN];
#pragma unroll
    for (int i = 0; i < TM; i++)
#pragma unroll
        for (int j = 0; j < TN; j++) acc[i][j] = 0.f;

    auto ldg = [&](int k0) {
        int g0 = row0 + ar, g1 = row0 + ar + 64;
        pa0 = (g0 < M) ? *(const float4*)(A + (size_t)g0 * K + k0 + ac)
                       : make_float4(0.f, 0.f, 0.f, 0.f);
        pa1 = (g1 < M) ? *(const float4*)(A + (size_t)g1 * K + k0 + ac)
                       : make_float4(0.f, 0.f, 0.f, 0.f);
        pb0 = *(const float4*)(B + (size_t)(k0 + br) * N + col0 + bc);
        pb1 = *(const float4*)(B + (size_t)(k0 + br + 8) * N + col0 + bc);
    };
    auto sts = [&](int buf) {
        As[buf][ac + 0][ar] = pa0.x; As[buf][ac + 1][ar] = pa0.y;
        As[buf][ac + 2][ar] = pa0.z; As[buf][ac + 3][ar] = pa0.w;
        As[buf][ac + 0][ar + 64] = pa1.x; As[buf][ac + 1][ar + 64] = pa1.y;
        As[buf][ac + 2][ar + 64] = pa1.z; As[buf][ac + 3][ar + 64] = pa1.w;
        *(float4*)&Bs[buf][br][bc] = pb0;
        *(float4*)&Bs[buf][br + 8][bc] = pb1;
    };

    ldg(0); sts(0); __syncthreads();
    int buf = 0;
    for (int k0 = 0; k0 < K; k0 += BK) {
        if (k0 + BK < K) ldg(k0 + BK);
#pragma unroll
        for (int k = 0; k < BK; k++) {
            float rm[TM], rn[TN];
#pragma unroll
            for (int i = 0; i < TM; i++) rm[i] = As[buf][k][trow + i];
#pragma unroll
            for (int j = 0; j < TN; j++) rn[j] = Bs[buf][k][tcol + j];
#pragma unroll
            for (int i = 0; i < TM; i++)
#pragma unroll
                for (int j = 0; j < TN; j++) acc[i][j] += rm[i] * rn[j];
        }
        if (k0 + BK < K) { sts(buf ^ 1); __syncthreads(); buf ^= 1; }
    }

#pragma unroll
    for (int i = 0; i < TM; i++) {
        int gr = row0 + trow + i;
        if (gr < M) {
#pragma unroll
            for (int j4 = 0; j4 < TN / 4; j4++) {
                float4 v = make_float4(acc[i][j4 * 4], acc[i][j4 * 4 + 1],
                                       acc[i][j4 * 4 + 2], acc[i][j4 * 4 + 3]);
                *(float4*)(C + (size_t)gr * N + col0 + tcol + j4 * 4) = v;
            }
        }
    }
}

// ---------------- W1 permutation: W1p[k][c*8+h] = W1[k][h*64+c] ----------------
__global__ void permW1_kernel(const float* __restrict__ W1, float* __restrict__ W1p) {
    int i = blockIdx.x * blockDim.x + threadIdx.x;
    if (i >= HID * W1OUT) return;
    int k = i >> 9;
    int j = i & 511;
    int hh = j >> 6, c = j & 63;
    W1p[(size_t)k * W1OUT + c * 8 + hh] = W1[i];
}

// ---------------- alpha layer0 ----------------
__global__ void alpha0_kernel(const float* __restrict__ h,
                              const float* __restrict__ av_s,
                              const float* __restrict__ av_d,
                              float* __restrict__ os, float* __restrict__ od) {
    int t = blockIdx.x * blockDim.x + threadIdx.x;
    int n = t >> 5, l = t & 31;
    if (n >= N_NODES) return;
    float4 hv = *(const float4*)(h + (size_t)n * HID + l * 4);
    int hh = l >> 2;
    float4 sa = *(const float4*)(av_s + hh * 16 + (l & 3) * 4);
    float4 da = *(const float4*)(av_d + hh * 16 + (l & 3) * 4);
    float ss = hv.x * sa.x + hv.y * sa.y + hv.z * sa.z + hv.w * sa.w;
    float sd = hv.x * da.x + hv.y * da.y + hv.z * da.z + hv.w * da.w;
    ss += __shfl_xor_sync(0xffffffffu, ss, 1);
    ss += __shfl_xor_sync(0xffffffffu, ss, 2);
    sd += __shfl_xor_sync(0xffffffffu, sd, 1);
    sd += __shfl_xor_sync(0xffffffffu, sd, 2);
    if ((l & 3) == 0) { os[n * 8 + hh] = ss; od[n * 8 + hh] = sd; }
}

// ---------------- alpha layer1 (h1 layout [n][c*8+h]) ----------------
__global__ void alpha1_kernel(const float* __restrict__ h,
                              const float* __restrict__ av_s,
                              const float* __restrict__ av_d,
                              float* __restrict__ os, float* __restrict__ od) {
    int t = blockIdx.x * blockDim.x + threadIdx.x;
    int n = t >> 5, l = t & 31;
    if (n >= N_NODES) return;
    float ss[8], sd[8];
#pragma unroll
    for (int hh = 0; hh < 8; hh++) { ss[hh] = 0.f; sd[hh] = 0.f; }
#pragma unroll
    for (int cc = 0; cc < 2; cc++) {
        int c = l + cc * 32;
        const float4* hp = (const float4*)(h + (size_t)n * W1OUT + c * 8);
        float4 v0 = hp[0], v1 = hp[1];
        float va[8] = {v0.x, v0.y, v0.z, v0.w, v1.x, v1.y, v1.z, v1.w};
#pragma unroll
        for (int hh = 0; hh < 8; hh++) {
            ss[hh] += va[hh] * av_s[hh * 64 + c];
            sd[hh] += va[hh] * av_d[hh * 64 + c];
        }
    }
#pragma unroll
    for (int hh = 0; hh < 8; hh++) {
#pragma unroll
        for (int o = 16; o; o >>= 1) {
            ss[hh] += __shfl_xor_sync(0xffffffffu, ss[hh], o);
            sd[hh] += __shfl_xor_sync(0xffffffffu, sd[hh], o);
        }
    }
    if (l == 0) {
#pragma unroll
        for (int hh = 0; hh < 8; hh++) { os[n * 8 + hh] = ss[hh]; od[n * 8 + hh] = sd[hh]; }
    }
}

// ---------------- edge exp in CSR order: alpha[p] = exp(leaky(as[src]+ad[dst])) ----------------
__global__ void edge_exp_kernel(const int* __restrict__ csr_src,
                                const int* __restrict__ csr_dst,
                                const float* __restrict__ as,
                                const float* __restrict__ ad,
                                float* __restrict__ alpha) {
    int p = blockIdx.x * blockDim.x + threadIdx.x;
    if (p >= N_EDGES) return;
    int src = csr_src[p];
    int dst = csr_dst[p];
    float4 s0 = ((const float4*)(as + src * 8))[0];
    float4 s1 = ((const float4*)(as + src * 8))[1];
    float4 d0 = ((const float4*)(ad + dst * 8))[0];
    float4 d1 = ((const float4*)(ad + dst * 8))[1];
    float v[8] = {s0.x + d0.x, s0.y + d0.y, s0.z + d0.z, s0.w + d0.w,
                  s1.x + d1.x, s1.y + d1.y, s1.z + d1.z, s1.w + d1.w};
#pragma unroll
    for (int h = 0; h < 8; h++) {
        float t = v[h];
        t = t > 0.f ? t : 0.2f * t;
        v[h] = expf(t);
    }
    ((float4*)(alpha + (size_t)p * 8))[0] = make_float4(v[0], v[1], v[2], v[3]);
    ((float4*)(alpha + (size_t)p * 8))[1] = make_float4(v[4], v[5], v[6], v[7]);
}

// ---------------- layer0 aggregation: block(128)/dst, inline den, fused bias+ELU ----------------
__global__ void agg0_kernel(const int* __restrict__ row_ptr,
                            const int* __restrict__ csr_src,
                            const float* __restrict__ alpha,
                            const float* __restrict__ h,
                            const float* __restrict__ b0,
                            float* __restrict__ out) {
    int dst = blockIdx.x;
    int idx = threadIdx.x;
    __shared__ float rden[8];
    __shared__ int s_src[128];
    int s = row_ptr[dst], e = row_ptr[dst + 1];
    // inline denominator: warp 0, lanes grouped by head (hh = lane&7, j = lane>>3)
    if (idx < 32) {
        int hh = idx & 7;
        float part = 0.f;
        for (int p = s + (idx >> 3); p < e; p += 4) part += alpha[(size_t)p * 8 + hh];
        part += __shfl_down_sync(0xffffffffu, part, 16);
        part += __shfl_down_sync(0xffffffffu, part, 8);
        if (idx < 8) rden[idx] = 1.f / (part + 1e-16f);
    }
    __syncthreads();
    int hh = idx >> 4;
    float r = rden[hh];
    float acc = 0.f;
    for (int base = s; base < e; base += 128) {
        int n = min(128, e - base);
        if (idx < n) s_src[idx] = csr_src[base + idx];
        __syncthreads();
#pragma unroll 4
        for (int i = 0; i < n; i++) {
            int src = s_src[i];
            float a = alpha[(size_t)(base + i) * 8 + hh];
            acc += a * h[(size_t)src * HID + idx];
        }
        __syncthreads();
    }
    float v = acc * r + b0[idx];
    out[(size_t)dst * HID + idx] = v > 0.f ? v : expm1f(v);
}

// ---------------- layer1 aggregation: block(64)/dst, inline den, fused mean+bias+log_softmax ----------------
__global__ void agg1_kernel(const int* __restrict__ row_ptr,
                            const int* __restrict__ csr_src,
                            const float* __restrict__ alpha,
                            const float* __restrict__ h,   // [n][c*8+hh]
                            const float* __restrict__ b1,
                            float* __restrict__ out) {
    int dst = blockIdx.x;
    int c = threadIdx.x;  // 0..63
    __shared__ float rden[8];
    __shared__ int s_src[64];
    __shared__ float red_mx[2];
    __shared__ float red_sm[2];
    int s = row_ptr[dst], e = row_ptr[dst + 1];
    if (c < 32) {
        int hh = c & 7;
        float part = 0.f;
        for (int p = s + (c >> 3); p < e; p += 4) part += alpha[(size_t)p * 8 + hh];
        part += __shfl_down_sync(0xffffffffu, part, 16);
        part += __shfl_down_sync(0xffffffffu, part, 8);
        if (c < 8) rden[c] = 1.f / (part + 1e-16f);
    }
    __syncthreads();
    float r0 = rden[0], r1 = rden[1], r2 = rden[2], r3 = rden[3];
    float r4 = rden[4], r5 = rden[5], r6 = rden[6], r7 = rden[7];
    float acc = 0.f;
    for (int base = s; base < e; base += 64) {
        int n = min(64, e - base);
        if (c < n) s_src[c] = csr_src[base + c];
        __syncthreads();
#pragma unroll 2
        for (int i = 0; i < n; i++) {
            int src = s_src[i];
            float4 a0 = ((const float4*)(alpha + (size_t)(base + i) * 8))[0];
            float4 a1 = ((const float4*)(alpha + (size_t)(base + i) * 8))[1];
            const float4* hp = (const float4*)(h + (size_t)src * W1OUT + c * 8);
            float4 v0 = hp[0], v1 = hp[1];
            acc += (a0.x * r0) * v0.x + (a0.y * r1) * v0.y + (a0.z * r2) * v0.z + (a0.w * r3) * v0.w
                 + (a1.x * r4) * v1.x + (a1.y * r5) * v1.y + (a1.z * r6) * v1.z + (a1.w * r7) * v1.w;
        }
        __syncthreads();
    }
    float v = acc * 0.125f + b1[c];
    float mx = v;
#pragma unroll
    for (int o = 16; o; o >>= 1) mx = fmaxf(mx, __shfl_xor_sync(0xffffffffu, mx, o));
    if ((c & 31) == 0) red_mx[c >> 5] = mx;
    __syncthreads();
    mx = fmaxf(red_mx[0], red_mx[1]);
    float ex = expf(v - mx);
    float sm = ex;
#pragma unroll
    for (int o = 16; o; o >>= 1) sm += __shfl_xor_sync(0xffffffffu, sm, o);
    if ((c & 31) == 0) red_sm[c >> 5] = sm;
    __syncthreads();
    float lse = mx + logf(red_sm[0] + red_sm[1]);
    out[(size_t)dst * NCLS + c] = v - lse;
}

// ---------------- launch ----------------
extern "C" void kernel_launch(void* const* d_in, const int* in_sizes, int n_in,
                              void* d_out, int out_size) {
    const float* x   = (const float*)d_in[0];
    const void*  ei  = d_in[1];
    const float* W0  = (const float*)d_in[2];
    const float* as0 = (const float*)d_in[3];
    const float* ad0 = (const float*)d_in[4];
    const float* b0  = (const float*)d_in[5];
    const float* W1  = (const float*)d_in[6];
    const float* as1 = (const float*)d_in[7];
    const float* ad1 = (const float*)d_in[8];
    const float* b1  = (const float*)d_in[9];
    float* out = (float*)d_out;

    float *h0, *h1, *as, *ad, *alpha, *agg0, *W1p;
    int *deg, *cur, *rowptr, *csrs, *csrd, *bsum, *boff;
    cudaGetSymbolAddress((void**)&h0,    g_h0);
    cudaGetSymbolAddress((void**)&h1,    g_h1);
    cudaGetSymbolAddress((void**)&as,    g_as);
    cudaGetSymbolAddress((void**)&ad,    g_ad);
    cudaGetSymbolAddress((void**)&alpha, g_alpha);
    cudaGetSymbolAddress((void**)&agg0,  g_agg0);
    cudaGetSymbolAddress((void**)&W1p,   g_W1p);
    cudaGetSymbolAddress((void**)&deg,   g_deg);
    cudaGetSymbolAddress((void**)&cur,   g_cur);
    cudaGetSymbolAddress((void**)&rowptr,g_rowptr);
    cudaGetSymbolAddress((void**)&csrs,  g_csr_src);
    cudaGetSymbolAddress((void**)&csrd,  g_csr_dst);
    cudaGetSymbolAddress((void**)&bsum,  g_bsum);
    cudaGetSymbolAddress((void**)&boff,  g_boff);

    const int TB = 256;
    const int EBLK = (N_EDGES + TB - 1) / TB;
    const int NBLK = (N_NODES + TB - 1) / TB;
    const int WBLK = (N_NODES * 32 + TB - 1) / TB;

    detect_kernel<<<1, 1>>>((const int*)ei);

    // CSR build
    zero_csr_kernel<<<NBLK, TB>>>(deg, cur);
    hist_kernel<<<EBLK, TB>>>(ei, deg);
    scanA_kernel<<<SCAN_G, SCAN_B>>>(deg, bsum);
    scanB_kernel<<<1, 256>>>(bsum, boff);
    scanC_kernel<<<SCAN_G, SCAN_B>>>(deg, boff, rowptr);
    fill_kernel<<<EBLK, TB>>>(ei, rowptr, cur, csrs, csrd);

    // ======== layer 0 ========
    sgemm_kernel<128, 128, 16, 8, 8><<<dim3(1, (N_NODES + 127) / 128), 256>>>(
        N_NODES, HID, 256, x, W0, h0);
    alpha0_kernel<<<WBLK, TB>>>(h0, as0, ad0, as, ad);
    edge_exp_kernel<<<EBLK, TB>>>(csrs, csrd, as, ad, alpha);
    agg0_kernel<<<N_NODES, 128>>>(rowptr, csrs, alpha, h0, b0, agg0);

    // ======== layer 1 ========
    permW1_kernel<<<(HID * W1OUT + TB - 1) / TB, TB>>>(W1, W1p);
    sgemm_kernel<128, 128, 16, 8, 8><<<dim3(W1OUT / 128, (N_NODES + 127) / 128), 256>>>(
        N_NODES, W1OUT, HID, agg0, W1p, h1);
    alpha1_kernel<<<WBLK, TB>>>(h1, as1, ad1, as, ad);
    edge_exp_kernel<<<EBLK, TB>>>(csrs, csrd, as, ad, alpha);
    agg1_kernel<<<N_NODES, 64>>>(rowptr, csrs, alpha, h1, b1, out);
}

// round 5
// speedup vs baseline: 2.6927x; 1.0248x over previous
#include <cuda_runtime.h>
#include <math.h>

#define N_NODES 50000
#define N_EDGES 600000
#define HEADS 8
#define HID 128
#define NCLS 64
#define SCAN_B 256
#define SCAN_G ((N_NODES + SCAN_B - 1) / SCAN_B)

typedef unsigned long long ull;

// ---------------- scratch ----------------
__device__ float g_h0[(size_t)N_NODES * HID];        // x @ W0
__device__ float g_z[(size_t)N_NODES * 1024];        // per-head aggregated agg0 ([n][h*128+k])
__device__ float g_as[N_NODES * HEADS];
__device__ float g_ad[N_NODES * HEADS];
__device__ float g_alpha[(size_t)N_EDGES * HEADS];   // CSR-position order
__device__ float g_agg0[(size_t)N_NODES * HID];      // layer0 output (post-ELU)
__device__ float g_W1s[1024 * NCLS];                 // stacked W1: [(h*128+k)][c]
__device__ float g_avs[HID * HEADS];                 // W1 folded with a_src1: [k][h]
__device__ float g_avd[HID * HEADS];
__device__ float g_zout[(size_t)N_NODES * NCLS];     // pre-softmax logits
__device__ int   g_deg[N_NODES];
__device__ int   g_cur[N_NODES];
__device__ int   g_rowptr[N_NODES + 1];
__device__ int   g_csr_src[N_EDGES];
__device__ int   g_csr_dst[N_EDGES];
__device__ int   g_bsum[SCAN_G];
__device__ int   g_boff[SCAN_G];
__device__ int   g_is64;

// ---------------- f32x2 helpers ----------------
__device__ __forceinline__ ull pk2(float lo, float hi) {
    ull r; asm("mov.b64 %0, {%1, %2};" : "=l"(r) : "f"(lo), "f"(hi)); return r;
}
__device__ __forceinline__ ull ffma2(ull a, ull b, ull c) {
    ull d; asm("fma.rn.f32x2 %0, %1, %2, %3;" : "=l"(d) : "l"(a), "l"(b), "l"(c)); return d;
}
__device__ __forceinline__ float2 upk2(ull p) {
    float2 v; asm("mov.b64 {%0, %1}, %2;" : "=f"(v.x), "=f"(v.y) : "l"(p)); return v;
}

// ---------------- init: zero deg/cur + dtype probe ----------------
__global__ void init_kernel(int* __restrict__ a, int* __restrict__ b,
                            const int* __restrict__ ei_raw) {
    int i = blockIdx.x * blockDim.x + threadIdx.x;
    if (i < N_NODES) { a[i] = 0; b[i] = 0; }
    if (i == 0) {
        int allz = 1;
#pragma unroll
        for (int j = 1; j < 64; j += 2)
            if (ei_raw[j] != 0) { allz = 0; break; }
        g_is64 = allz;
    }
}
__device__ __forceinline__ int edge_src(const void* ei, int e) {
    if (g_is64) return (int)((const long long*)ei)[e];
    return ((const int*)ei)[e];
}
__device__ __forceinline__ int edge_dst(const void* ei, int e) {
    if (g_is64) return (int)((const long long*)ei)[N_EDGES + e];
    return ((const int*)ei)[N_EDGES + e];
}

// ---------------- CSR build ----------------
__global__ void hist_kernel(const void* __restrict__ ei, int* __restrict__ deg) {
    int e = blockIdx.x * blockDim.x + threadIdx.x;
    if (e >= N_EDGES) return;
    atomicAdd(&deg[edge_dst(ei, e)], 1);
}
__global__ void scanA_kernel(const int* __restrict__ deg, int* __restrict__ bsum) {
    __shared__ int ws[8];
    int tid = threadIdx.x, lane = tid & 31, wid = tid >> 5;
    int i = blockIdx.x * SCAN_B + tid;
    int x = (i < N_NODES) ? deg[i] : 0;
#pragma unroll
    for (int o = 16; o; o >>= 1) x += __shfl_down_sync(0xffffffffu, x, o);
    if (lane == 0) ws[wid] = x;
    __syncthreads();
    if (tid == 0) {
        int t = 0;
#pragma unroll
        for (int j = 0; j < 8; j++) t += ws[j];
        bsum[blockIdx.x] = t;
    }
}
__global__ void scanB_kernel(const int* __restrict__ bsum, int* __restrict__ boff) {
    __shared__ int ws[8];
    int tid = threadIdx.x, lane = tid & 31, wid = tid >> 5;
    int v = (tid < SCAN_G) ? bsum[tid] : 0;
    int x = v;
#pragma unroll
    for (int o = 1; o < 32; o <<= 1) {
        int t = __shfl_up_sync(0xffffffffu, x, o);
        if (lane >= o) x += t;
    }
    if (lane == 31) ws[wid] = x;
    __syncthreads();
    if (tid == 0) {
        int run = 0;
#pragma unroll
        for (int j = 0; j < 8; j++) { int t = ws[j]; ws[j] = run; run += t; }
    }
    __syncthreads();
    if (tid < SCAN_G) boff[tid] = x - v + ws[wid];
}
__global__ void scanC_kernel(const int* __restrict__ deg, const int* __restrict__ boff,
                             int* __restrict__ row_ptr) {
    __shared__ int ws[8];
    int tid = threadIdx.x, lane = tid & 31, wid = tid >> 5;
    int i = blockIdx.x * SCAN_B + tid;
    int v = (i < N_NODES) ? deg[i] : 0;
    int x = v;
#pragma unroll
    for (int o = 1; o < 32; o <<= 1) {
        int t = __shfl_up_sync(0xffffffffu, x, o);
        if (lane >= o) x += t;
    }
    if (lane == 31) ws[wid] = x;
    __syncthreads();
    if (tid == 0) {
        int run = 0;
#pragma unroll
        for (int j = 0; j < 8; j++) { int t = ws[j]; ws[j] = run; run += t; }
    }
    __syncthreads();
    if (i < N_NODES) row_ptr[i] = x - v + ws[wid] + boff[blockIdx.x];
    if (blockIdx.x == 0 && tid == 0) row_ptr[N_NODES] = N_EDGES;
}
__global__ void fill_kernel(const void* __restrict__ ei, const int* __restrict__ row_ptr,
                            int* __restrict__ cur, int* __restrict__ csr_src,
                            int* __restrict__ csr_dst) {
    int e = blockIdx.x * blockDim.x + threadIdx.x;
    if (e >= N_EDGES) return;
    int dst = edge_dst(ei, e);
    int src = edge_src(ei, e);
    int p = row_ptr[dst] + atomicAdd(&cur[dst], 1);
    csr_src[p] = src;
    csr_dst[p] = dst;
}

// ---------------- f32x2 SGEMM: C[M,N] = A[M,K] @ B[K,N]; BM=128, BK=16, TM=8 ----------------
template <int BN, int TN>
__global__ void sgemm2_kernel(int M, int N, int K,
                              const float* __restrict__ A,
                              const float* __restrict__ B,
                              float* __restrict__ C) {
    constexpr int BM = 128, BK = 16, TM = 8;
    __shared__ float As[2][BK][BM + 4];
    __shared__ float Bs[2][BK][BN];
    const int tid = threadIdx.x;
    const int row0 = blockIdx.y * BM;
    const int col0 = blockIdx.x * BN;
    const int ar = tid >> 2;
    const int ac = (tid & 3) * 4;
    const int trow = (tid / (BN / TN)) * TM;
    const int tcol = (tid % (BN / TN)) * TN;

    float4 pa0, pa1, pb0, pb1;
    ull acc2[4][TN];
#pragma unroll
    for (int t = 0; t < 4; t++)
#pragma unroll
        for (int j = 0; j < TN; j++) acc2[t][j] = 0ull;

    auto ldg = [&](int k0) {
        int g0 = row0 + ar, g1 = row0 + ar + 64;
        pa0 = (g0 < M) ? *(const float4*)(A + (size_t)g0 * K + k0 + ac)
                       : make_float4(0.f, 0.f, 0.f, 0.f);
        pa1 = (g1 < M) ? *(const float4*)(A + (size_t)g1 * K + k0 + ac)
                       : make_float4(0.f, 0.f, 0.f, 0.f);
        if (BN == 128) {
            int br = tid >> 5, bc = (tid & 31) * 4;
            pb0 = *(const float4*)(B + (size_t)(k0 + br) * N + col0 + bc);
            pb1 = *(const float4*)(B + (size_t)(k0 + br + 8) * N + col0 + bc);
        } else {  // BN == 64
            int br = tid >> 4, bc = (tid & 15) * 4;
            pb0 = *(const float4*)(B + (size_t)(k0 + br) * N + col0 + bc);
        }
    };
    auto sts = [&](int buf) {
        As[buf][ac + 0][ar] = pa0.x; As[buf][ac + 1][ar] = pa0.y;
        As[buf][ac + 2][ar] = pa0.z; As[buf][ac + 3][ar] = pa0.w;
        As[buf][ac + 0][ar + 64] = pa1.x; As[buf][ac + 1][ar + 64] = pa1.y;
        As[buf][ac + 2][ar + 64] = pa1.z; As[buf][ac + 3][ar + 64] = pa1.w;
        if (BN == 128) {
            int br = tid >> 5, bc = (tid & 31) * 4;
            *(float4*)&Bs[buf][br][bc] = pb0;
            *(float4*)&Bs[buf][br + 8][bc] = pb1;
        } else {
            int br = tid >> 4, bc = (tid & 15) * 4;
            *(float4*)&Bs[buf][br][bc] = pb0;
        }
    };

    ldg(0); sts(0); __syncthreads();
    int buf = 0;
    for (int k0 = 0; k0 < K; k0 += BK) {
        if (k0 + BK < K) ldg(k0 + BK);
#pragma unroll
        for (int k = 0; k < BK; k++) {
            float4 a0 = *(const float4*)&As[buf][k][trow];
            float4 a1 = *(const float4*)&As[buf][k][trow + 4];
            ull am[4] = {pk2(a0.x, a0.y), pk2(a0.z, a0.w),
                         pk2(a1.x, a1.y), pk2(a1.z, a1.w)};
            float rn[TN];
#pragma unroll
            for (int j4 = 0; j4 < TN / 4; j4++) {
                float4 bv = *(const float4*)&Bs[buf][k][tcol + j4 * 4];
                rn[j4 * 4 + 0] = bv.x; rn[j4 * 4 + 1] = bv.y;
                rn[j4 * 4 + 2] = bv.z; rn[j4 * 4 + 3] = bv.w;
            }
            ull bn[TN];
#pragma unroll
            for (int j = 0; j < TN; j++) bn[j] = pk2(rn[j], rn[j]);
#pragma unroll
            for (int t = 0; t < 4; t++)
#pragma unroll
                for (int j = 0; j < TN; j++)
                    acc2[t][j] = ffma2(am[t], bn[j], acc2[t][j]);
        }
        if (k0 + BK < K) { sts(buf ^ 1); __syncthreads(); buf ^= 1; }
    }

#pragma unroll
    for (int t = 0; t < 4; t++) {
        float2 v[TN];
#pragma unroll
        for (int j = 0; j < TN; j++) v[j] = upk2(acc2[t][j]);
        int r0 = row0 + trow + 2 * t;
        int r1 = r0 + 1;
        if (r0 < M) {
#pragma unroll
            for (int j4 = 0; j4 < TN / 4; j4++) {
                float4 o = make_float4(v[j4 * 4].x, v[j4 * 4 + 1].x,
                                       v[j4 * 4 + 2].x, v[j4 * 4 + 3].x);
                *(float4*)(C + (size_t)r0 * N + col0 + tcol + j4 * 4) = o;
            }
        }
        if (r1 < M) {
#pragma unroll
            for (int j4 = 0; j4 < TN / 4; j4++) {
                float4 o = make_float4(v[j4 * 4].y, v[j4 * 4 + 1].y,
                                       v[j4 * 4 + 2].y, v[j4 * 4 + 3].y);
                *(float4*)(C + (size_t)r1 * N + col0 + tcol + j4 * 4) = o;
            }
        }
    }
}

// ---------------- alpha layer0: warp per node ----------------
__global__ void alpha0_kernel(const float* __restrict__ h,
                              const float* __restrict__ av_s,
                              const float* __restrict__ av_d,
                              float* __restrict__ os, float* __restrict__ od) {
    int t = blockIdx.x * blockDim.x + threadIdx.x;
    int n = t >> 5, l = t & 31;
    if (n >= N_NODES) return;
    float4 hv = *(const float4*)(h + (size_t)n * HID + l * 4);
    int hh = l >> 2;
    float4 sa = *(const float4*)(av_s + hh * 16 + (l & 3) * 4);
    float4 da = *(const float4*)(av_d + hh * 16 + (l & 3) * 4);
    float ss = hv.x * sa.x + hv.y * sa.y + hv.z * sa.z + hv.w * sa.w;
    float sd = hv.x * da.x + hv.y * da.y + hv.z * da.z + hv.w * da.w;
    ss += __shfl_xor_sync(0xffffffffu, ss, 1);
    ss += __shfl_xor_sync(0xffffffffu, ss, 2);
    sd += __shfl_xor_sync(0xffffffffu, sd, 1);
    sd += __shfl_xor_sync(0xffffffffu, sd, 2);
    if ((l & 3) == 0) { os[n * 8 + hh] = ss; od[n * 8 + hh] = sd; }
}

// ---------------- edge exp in CSR order ----------------
__global__ void edge_exp_kernel(const int* __restrict__ csr_src,
                                const int* __restrict__ csr_dst,
                                const float* __restrict__ as,
                                const float* __restrict__ ad,
                                float* __restrict__ alpha) {
    int p = blockIdx.x * blockDim.x + threadIdx.x;
    if (p >= N_EDGES) return;
    int src = csr_src[p];
    int dst = csr_dst[p];
    float4 s0 = ((const float4*)(as + src * 8))[0];
    float4 s1 = ((const float4*)(as + src * 8))[1];
    float4 d0 = ((const float4*)(ad + dst * 8))[0];
    float4 d1 = ((const float4*)(ad + dst * 8))[1];
    float v[8] = {s0.x + d0.x, s0.y + d0.y, s0.z + d0.z, s0.w + d0.w,
                  s1.x + d1.x, s1.y + d1.y, s1.z + d1.z, s1.w + d1.w};
#pragma unroll
    for (int h = 0; h < 8; h++) {
        float t = v[h];
        t = t > 0.f ? t : 0.2f * t;
        v[h] = expf(t);
    }
    ((float4*)(alpha + (size_t)p * 8))[0] = make_float4(v[0], v[1], v[2], v[3]);
    ((float4*)(alpha + (size_t)p * 8))[1] = make_float4(v[4], v[5], v[6], v[7]);
}

// ---------------- layer0 aggregation: block(128)/dst, inline den, fused bias+ELU ----------------
__global__ void agg0_kernel(const int* __restrict__ row_ptr,
                            const int* __restrict__ csr_src,
                            const float* __restrict__ alpha,
                            const float* __restrict__ h,
                            const float* __restrict__ b0,
                            float* __restrict__ out) {
    int dst = blockIdx.x;
    int idx = threadIdx.x;
    __shared__ float rden[8];
    __shared__ int s_src[128];
    int s = row_ptr[dst], e = row_ptr[dst + 1];
    if (idx < 32) {
        int hh = idx & 7;
        float part = 0.f;
        for (int p = s + (idx >> 3); p < e; p += 4) part += alpha[(size_t)p * 8 + hh];
        part += __shfl_down_sync(0xffffffffu, part, 16);
        part += __shfl_down_sync(0xffffffffu, part, 8);
        if (idx < 8) rden[idx] = 1.f / (part + 1e-16f);
    }
    __syncthreads();
    int hh = idx >> 4;
    float r = rden[hh];
    float acc = 0.f;
    for (int base = s; base < e; base += 128) {
        int n = min(128, e - base);
        if (idx < n) s_src[idx] = csr_src[base + idx];
        __syncthreads();
#pragma unroll 4
        for (int i = 0; i < n; i++) {
            int src = s_src[i];
            float a = alpha[(size_t)(base + i) * 8 + hh];
            acc += a * h[(size_t)src * HID + idx];
        }
        __syncthreads();
    }
    float v = acc * r + b0[idx];
    out[(size_t)dst * HID + idx] = v > 0.f ? v : expm1f(v);
}

// ---------------- fold W1 with attention vectors: avs[k][h] = sum_c W1[k][h*64+c]*a[h][c] ----------------
__global__ void gemv_w1a_kernel(const float* __restrict__ W1,
                                const float* __restrict__ a_s,
                                const float* __restrict__ a_d,
                                float* __restrict__ avs, float* __restrict__ avd) {
    int o = blockIdx.x * blockDim.x + threadIdx.x;
    if (o >= HID * HEADS) return;
    int k = o >> 3, hh = o & 7;
    const float* wrow = W1 + (size_t)k * 512 + hh * 64;
    const float* sv = a_s + hh * 64;
    const float* dv = a_d + hh * 64;
    float ss = 0.f, sd = 0.f;
#pragma unroll 16
    for (int c = 0; c < 64; c++) {
        float w = wrow[c];
        ss += w * sv[c];
        sd += w * dv[c];
    }
    avs[k * 8 + hh] = ss;
    avd[k * 8 + hh] = sd;
}

// ---------------- alpha layer1: block(128) per 8 nodes, smem staged ----------------
__global__ void alpha1_kernel(const float* __restrict__ agg0,
                              const float* __restrict__ avs,
                              const float* __restrict__ avd,
                              float* __restrict__ os, float* __restrict__ od) {
    __shared__ float s_a[8][HID + 1];
    __shared__ float s_t[HID][16];  // [k][out]: out 0..7 = avs, 8..15 = avd
    int tid = threadIdx.x;
    int n0 = blockIdx.x * 8;
    // stage tables
#pragma unroll
    for (int i = tid; i < HID * 8; i += 128) {
        int k = i >> 3, hh = i & 7;
        s_t[k][hh] = avs[i];
        s_t[k][8 + hh] = avd[i];
    }
    // stage 8 node rows (coalesced)
#pragma unroll
    for (int r = 0; r < 8; r++) {
        int n = n0 + r;
        float v = (n < N_NODES) ? agg0[(size_t)n * HID + tid] : 0.f;
        s_a[r][tid] = v;
    }
    __syncthreads();
    int node = tid >> 4;       // 0..7
    int outp = tid & 15;       // 0..15
    float acc = 0.f;
#pragma unroll 8
    for (int k = 0; k < HID; k++) acc += s_a[node][k] * s_t[k][outp];
    int n = n0 + node;
    if (n < N_NODES) {
        if (outp < 8) os[n * 8 + outp] = acc;
        else od[n * 8 + (outp - 8)] = acc;
    }
}

// ---------------- layer1 per-head aggregation of agg0 rows: z[dst][h*128+k] ----------------
__global__ void aggz_kernel(const int* __restrict__ row_ptr,
                            const int* __restrict__ csr_src,
                            const float* __restrict__ alpha,
                            const float* __restrict__ agg0,
                            float* __restrict__ z) {
    int dst = blockIdx.x;
    int idx = threadIdx.x;  // k dimension 0..127
    __shared__ float rden[8];
    __shared__ int s_src[128];
    __shared__ float s_al[128 * 8];
    int s = row_ptr[dst], e = row_ptr[dst + 1];
    if (idx < 32) {
        int hh = idx & 7;
        float part = 0.f;
        for (int p = s + (idx >> 3); p < e; p += 4) part += alpha[(size_t)p * 8 + hh];
        part += __shfl_down_sync(0xffffffffu, part, 16);
        part += __shfl_down_sync(0xffffffffu, part, 8);
        if (idx < 8) rden[idx] = 0.125f / (part + 1e-16f);
    }
    float acc[8];
#pragma unroll
    for (int h = 0; h < 8; h++) acc[h] = 0.f;
    __syncthreads();
    for (int base = s; base < e; base += 128) {
        int n = min(128, e - base);
        if (idx < n) s_src[idx] = csr_src[base + idx];
        // stage alpha tile: n*8 floats
        for (int i = idx * 4; i < n * 8; i += 128 * 4)
            *(float4*)&s_al[i] = *(const float4*)&alpha[(size_t)base * 8 + i];
        __syncthreads();
#pragma unroll 2
        for (int i = 0; i < n; i++) {
            float v = agg0[(size_t)s_src[i] * HID + idx];
#pragma unroll
            for (int h = 0; h < 8; h++) acc[h] += s_al[i * 8 + h] * v;
        }
        __syncthreads();
    }
#pragma unroll
    for (int h = 0; h < 8; h++)
        z[(size_t)dst * 1024 + h * HID + idx] = acc[h] * rden[h];
}

// ---------------- stack W1: W1s[(h*128+k)][c] = W1[k][h*64+c] ----------------
__global__ void permW1s_kernel(const float* __restrict__ W1, float* __restrict__ W1s) {
    int i = blockIdx.x * blockDim.x + threadIdx.x;
    if (i >= HID * 512) return;
    int k = i >> 9;
    int j = i & 511;
    int hh = j >> 6, c = j & 63;
    W1s[(size_t)(hh * HID + k) * NCLS + c] = W1[i];
}

// ---------------- finalize: out = log_softmax(zout + b1); warp per node ----------------
__global__ void finalize_kernel(const float* __restrict__ zo,
                                const float* __restrict__ b1,
                                float* __restrict__ out) {
    int t = blockIdx.x * blockDim.x + threadIdx.x;
    int n = t >> 5, lane = t & 31;
    if (n >= N_NODES) return;
    float v0 = zo[(size_t)n * NCLS + lane] + b1[lane];
    float v1 = zo[(size_t)n * NCLS + lane + 32] + b1[lane + 32];
    float mx = fmaxf(v0, v1);
#pragma unroll
    for (int o = 16; o; o >>= 1) mx = fmaxf(mx, __shfl_xor_sync(0xffffffffu, mx, o));
    float s = expf(v0 - mx) + expf(v1 - mx);
#pragma unroll
    for (int o = 16; o; o >>= 1) s += __shfl_xor_sync(0xffffffffu, s, o);
    float lse = mx + logf(s);
    out[(size_t)n * NCLS + lane] = v0 - lse;
    out[(size_t)n * NCLS + lane + 32] = v1 - lse;
}

// ---------------- launch ----------------
extern "C" void kernel_launch(void* const* d_in, const int* in_sizes, int n_in,
                              void* d_out, int out_size) {
    const float* x   = (const float*)d_in[0];
    const void*  ei  = d_in[1];
    const float* W0  = (const float*)d_in[2];
    const float* as0 = (const float*)d_in[3];
    const float* ad0 = (const float*)d_in[4];
    const float* b0  = (const float*)d_in[5];
    const float* W1  = (const float*)d_in[6];
    const float* as1 = (const float*)d_in[7];
    const float* ad1 = (const float*)d_in[8];
    const float* b1  = (const float*)d_in[9];
    float* out = (float*)d_out;

    float *h0, *z, *as, *ad, *alpha, *agg0, *W1s, *avs, *avd, *zout;
    int *deg, *cur, *rowptr, *csrs, *csrd, *bsum, *boff;
    cudaGetSymbolAddress((void**)&h0,    g_h0);
    cudaGetSymbolAddress((void**)&z,     g_z);
    cudaGetSymbolAddress((void**)&as,    g_as);
    cudaGetSymbolAddress((void**)&ad,    g_ad);
    cudaGetSymbolAddress((void**)&alpha, g_alpha);
    cudaGetSymbolAddress((void**)&agg0,  g_agg0);
    cudaGetSymbolAddress((void**)&W1s,   g_W1s);
    cudaGetSymbolAddress((void**)&avs,   g_avs);
    cudaGetSymbolAddress((void**)&avd,   g_avd);
    cudaGetSymbolAddress((void**)&zout,  g_zout);
    cudaGetSymbolAddress((void**)&deg,   g_deg);
    cudaGetSymbolAddress((void**)&cur,   g_cur);
    cudaGetSymbolAddress((void**)&rowptr,g_rowptr);
    cudaGetSymbolAddress((void**)&csrs,  g_csr_src);
    cudaGetSymbolAddress((void**)&csrd,  g_csr_dst);
    cudaGetSymbolAddress((void**)&bsum,  g_bsum);
    cudaGetSymbolAddress((void**)&boff,  g_boff);

    const int TB = 256;
    const int EBLK = (N_EDGES + TB - 1) / TB;
    const int NBLK = (N_NODES + TB - 1) / TB;
    const int WBLK = (N_NODES * 32 + TB - 1) / TB;

    // 1-5: CSR prefix
    init_kernel<<<NBLK, TB>>>(deg, cur, (const int*)ei);
    hist_kernel<<<EBLK, TB>>>(ei, deg);
    scanA_kernel<<<SCAN_G, SCAN_B>>>(deg, bsum);
    scanB_kernel<<<1, 256>>>(bsum, boff);
    scanC_kernel<<<SCAN_G, SCAN_B>>>(deg, boff, rowptr);
    // 6: layer0 GEMM (profiled launch)
    sgemm2_kernel<128, 8><<<dim3(1, (N_NODES + 127) / 128), 256>>>(
        N_NODES, HID, 256, x, W0, h0);
    // 7: CSR fill
    fill_kernel<<<EBLK, TB>>>(ei, rowptr, cur, csrs, csrd);

    // layer 0
    alpha0_kernel<<<WBLK, TB>>>(h0, as0, ad0, as, ad);
    edge_exp_kernel<<<EBLK, TB>>>(csrs, csrd, as, ad, alpha);
    agg0_kernel<<<N_NODES, 128>>>(rowptr, csrs, alpha, h0, b0, agg0);

    // layer 1
    gemv_w1a_kernel<<<(HID * HEADS + TB - 1) / TB, TB>>>(W1, as1, ad1, avs, avd);
    alpha1_kernel<<<(N_NODES + 7) / 8, 128>>>(agg0, avs, avd, as, ad);
    edge_exp_kernel<<<EBLK, TB>>>(csrs, csrd, as, ad, alpha);
    aggz_kernel<<<N_NODES, 128>>>(rowptr, csrs, alpha, agg0, z);
    permW1s_kernel<<<(HID * 512 + TB - 1) / TB, TB>>>(W1, W1s);
    sgemm2_kernel<64, 4><<<dim3(1, (N_NODES + 127) / 128), 256>>>(
        N_NODES, NCLS, 1024, z, W1s, zout);
    finalize_kernel<<<WBLK, TB>>>(zout, b1, out);
}

// round 6
// speedup vs baseline: 2.7189x; 1.0097x over previous
#include <cuda_runtime.h>
#include <math.h>

#define N_NODES 50000
#define N_EDGES 600000
#define HEADS 8
#define HID 128
#define NCLS 64
#define SCAN_B 256
#define SCAN_G ((N_NODES + SCAN_B - 1) / SCAN_B)

typedef unsigned long long ull;

// ---------------- scratch ----------------
__device__ float g_h0[(size_t)N_NODES * HID];
__device__ float g_z[(size_t)N_NODES * 1024];
__device__ float g_as[N_NODES * HEADS];
__device__ float g_ad[N_NODES * HEADS];
__device__ float g_agg0[(size_t)N_NODES * HID];
__device__ float g_W1s[1024 * NCLS];
__device__ float g_avs[HID * HEADS];
__device__ float g_avd[HID * HEADS];
__device__ float g_zout[(size_t)N_NODES * NCLS];
__device__ int   g_deg[N_NODES];
__device__ int   g_cur[N_NODES];
__device__ int   g_rowptr[N_NODES + 1];
__device__ int   g_csr_src[N_EDGES];
__device__ int   g_csr_dst[N_EDGES];
__device__ int   g_bsum[SCAN_G];
__device__ int   g_boff[SCAN_G];
__device__ int   g_is64;

// ---------------- f32x2 helpers ----------------
__device__ __forceinline__ ull ffma2(ull a, ull b, ull c) {
    ull d; asm("fma.rn.f32x2 %0, %1, %2, %3;" : "=l"(d) : "l"(a), "l"(b), "l"(c)); return d;
}
__device__ __forceinline__ float2 upk2(ull p) {
    float2 v; asm("mov.b64 {%0, %1}, %2;" : "=f"(v.x), "=f"(v.y) : "l"(p)); return v;
}

// ---------------- init + dtype probe ----------------
__global__ void init_kernel(int* __restrict__ a, int* __restrict__ b,
                            const int* __restrict__ ei_raw) {
    int i = blockIdx.x * blockDim.x + threadIdx.x;
    if (i < N_NODES) { a[i] = 0; b[i] = 0; }
    if (i == 0) {
        int allz = 1;
#pragma unroll
        for (int j = 1; j < 64; j += 2)
            if (ei_raw[j] != 0) { allz = 0; break; }
        g_is64 = allz;
    }
}
__device__ __forceinline__ int edge_src(const void* ei, int e) {
    if (g_is64) return (int)((const long long*)ei)[e];
    return ((const int*)ei)[e];
}
__device__ __forceinline__ int edge_dst(const void* ei, int e) {
    if (g_is64) return (int)((const long long*)ei)[N_EDGES + e];
    return ((const int*)ei)[N_EDGES + e];
}

// ---------------- CSR build ----------------
__global__ void hist_kernel(const void* __restrict__ ei, int* __restrict__ deg) {
    int e = blockIdx.x * blockDim.x + threadIdx.x;
    if (e >= N_EDGES) return;
    atomicAdd(&deg[edge_dst(ei, e)], 1);
}
__global__ void scanA_kernel(const int* __restrict__ deg, int* __restrict__ bsum) {
    __shared__ int ws[8];
    int tid = threadIdx.x, lane = tid & 31, wid = tid >> 5;
    int i = blockIdx.x * SCAN_B + tid;
    int x = (i < N_NODES) ? deg[i] : 0;
#pragma unroll
    for (int o = 16; o; o >>= 1) x += __shfl_down_sync(0xffffffffu, x, o);
    if (lane == 0) ws[wid] = x;
    __syncthreads();
    if (tid == 0) {
        int t = 0;
#pragma unroll
        for (int j = 0; j < 8; j++) t += ws[j];
        bsum[blockIdx.x] = t;
    }
}
__global__ void scanB_kernel(const int* __restrict__ bsum, int* __restrict__ boff) {
    __shared__ int ws[8];
    int tid = threadIdx.x, lane = tid & 31, wid = tid >> 5;
    int v = (tid < SCAN_G) ? bsum[tid] : 0;
    int x = v;
#pragma unroll
    for (int o = 1; o < 32; o <<= 1) {
        int t = __shfl_up_sync(0xffffffffu, x, o);
        if (lane >= o) x += t;
    }
    if (lane == 31) ws[wid] = x;
    __syncthreads();
    if (tid == 0) {
        int run = 0;
#pragma unroll
        for (int j = 0; j < 8; j++) { int t = ws[j]; ws[j] = run; run += t; }
    }
    __syncthreads();
    if (tid < SCAN_G) boff[tid] = x - v + ws[wid];
}
__global__ void scanC_kernel(const int* __restrict__ deg, const int* __restrict__ boff,
                             int* __restrict__ row_ptr) {
    __shared__ int ws[8];
    int tid = threadIdx.x, lane = tid & 31, wid = tid >> 5;
    int i = blockIdx.x * SCAN_B + tid;
    int v = (i < N_NODES) ? deg[i] : 0;
    int x = v;
#pragma unroll
    for (int o = 1; o < 32; o <<= 1) {
        int t = __shfl_up_sync(0xffffffffu, x, o);
        if (lane >= o) x += t;
    }
    if (lane == 31) ws[wid] = x;
    __syncthreads();
    if (tid == 0) {
        int run = 0;
#pragma unroll
        for (int j = 0; j < 8; j++) { int t = ws[j]; ws[j] = run; run += t; }
    }
    __syncthreads();
    if (i < N_NODES) row_ptr[i] = x - v + ws[wid] + boff[blockIdx.x];
    if (blockIdx.x == 0 && tid == 0) row_ptr[N_NODES] = N_EDGES;
}
__global__ void fill_kernel(const void* __restrict__ ei, const int* __restrict__ row_ptr,
                            int* __restrict__ cur, int* __restrict__ csr_src,
                            int* __restrict__ csr_dst) {
    int e = blockIdx.x * blockDim.x + threadIdx.x;
    if (e >= N_EDGES) return;
    int dst = edge_dst(ei, e);
    int src = edge_src(ei, e);
    int p = row_ptr[dst] + atomicAdd(&cur[dst], 1);
    csr_src[p] = src;
    csr_dst[p] = dst;
}

// ---------------- f32x2 SGEMM, duplicated-A smem, column-paired accumulators ----------------
// C[M,N] = A[M,K] @ B[K,N]; BM=128, BK=16, TM=8; zero pack-MOVs in inner loop.
template <int BN, int TN>
__global__ void sgemm2_kernel(int M, int N, int K,
                              const float* __restrict__ A,
                              const float* __restrict__ B,
                              float* __restrict__ C) {
    constexpr int BM = 128, BK = 16, TM = 8;
    constexpr int AST = 2 * BM;  // duplicated row stride (words)
    __shared__ float As2[2][BK][AST];
    __shared__ float Bs[2][BK][BN];
    const int tid = threadIdx.x;
    const int row0 = blockIdx.y * BM;
    const int col0 = blockIdx.x * BN;
    const int ar = tid >> 2;
    const int ac = (tid & 3) * 4;
    const int trow = (tid / (BN / TN)) * TM;
    const int tcol = (tid % (BN / TN)) * TN;

    float4 pa0, pa1, pb0, pb1;
    ull acc2[TM][TN / 2];
#pragma unroll
    for (int i = 0; i < TM; i++)
#pragma unroll
        for (int j = 0; j < TN / 2; j++) acc2[i][j] = 0ull;

    auto ldg = [&](int k0) {
        int g0 = row0 + ar, g1 = row0 + ar + 64;
        pa0 = (g0 < M) ? *(const float4*)(A + (size_t)g0 * K + k0 + ac)
                       : make_float4(0.f, 0.f, 0.f, 0.f);
        pa1 = (g1 < M) ? *(const float4*)(A + (size_t)g1 * K + k0 + ac)
                       : make_float4(0.f, 0.f, 0.f, 0.f);
        if (BN == 128) {
            int br = tid >> 5, bc = (tid & 31) * 4;
            pb0 = *(const float4*)(B + (size_t)(k0 + br) * N + col0 + bc);
            pb1 = *(const float4*)(B + (size_t)(k0 + br + 8) * N + col0 + bc);
        } else {  // BN == 64
            int br = tid >> 4, bc = (tid & 15) * 4;
            pb0 = *(const float4*)(B + (size_t)(k0 + br) * N + col0 + bc);
        }
    };
    auto sts = [&](int buf) {
        const float* va0 = &pa0.x;
        const float* va1 = &pa1.x;
#pragma unroll
        for (int i = 0; i < 4; i++) {
            *(float2*)&As2[buf][ac + i][2 * ar] = make_float2(va0[i], va0[i]);
            *(float2*)&As2[buf][ac + i][2 * (ar + 64)] = make_float2(va1[i], va1[i]);
        }
        if (BN == 128) {
            int br = tid >> 5, bc = (tid & 31) * 4;
            *(float4*)&Bs[buf][br][bc] = pb0;
            *(float4*)&Bs[buf][br + 8][bc] = pb1;
        } else {
            int br = tid >> 4, bc = (tid & 15) * 4;
            *(float4*)&Bs[buf][br][bc] = pb0;
        }
    };

    ldg(0); sts(0); __syncthreads();
    int buf = 0;
    for (int k0 = 0; k0 < K; k0 += BK) {
        if (k0 + BK < K) ldg(k0 + BK);
#pragma unroll
        for (int k = 0; k < BK; k++) {
            ull am[TM];
#pragma unroll
            for (int r = 0; r < TM / 2; r++) {
                ulonglong2 a2 = *(const ulonglong2*)&As2[buf][k][2 * trow + 4 * r];
                am[2 * r] = a2.x;
                am[2 * r + 1] = a2.y;
            }
            ull bp[TN / 2];
#pragma unroll
            for (int j = 0; j < TN / 4; j++) {
                ulonglong2 b2 = *(const ulonglong2*)&Bs[buf][k][tcol + 4 * j];
                bp[2 * j] = b2.x;
                bp[2 * j + 1] = b2.y;
            }
#pragma unroll
            for (int i = 0; i < TM; i++)
#pragma unroll
                for (int j = 0; j < TN / 2; j++)
                    acc2[i][j] = ffma2(am[i], bp[j], acc2[i][j]);
        }
        if (k0 + BK < K) { sts(buf ^ 1); __syncthreads(); buf ^= 1; }
    }

#pragma unroll
    for (int i = 0; i < TM; i++) {
        int gr = row0 + trow + i;
        if (gr < M) {
#pragma unroll
            for (int j4 = 0; j4 < TN / 4; j4++) {
                float2 lo = upk2(acc2[i][2 * j4]);
                float2 hi = upk2(acc2[i][2 * j4 + 1]);
                *(float4*)(C + (size_t)gr * N + col0 + tcol + 4 * j4) =
                    make_float4(lo.x, lo.y, hi.x, hi.y);
            }
        }
    }
}

// ---------------- alpha layer0: warp per node ----------------
__global__ void alpha0_kernel(const float* __restrict__ h,
                              const float* __restrict__ av_s,
                              const float* __restrict__ av_d,
                              float* __restrict__ os, float* __restrict__ od) {
    int t = blockIdx.x * blockDim.x + threadIdx.x;
    int n = t >> 5, l = t & 31;
    if (n >= N_NODES) return;
    float4 hv = *(const float4*)(h + (size_t)n * HID + l * 4);
    int hh = l >> 2;
    float4 sa = *(const float4*)(av_s + hh * 16 + (l & 3) * 4);
    float4 da = *(const float4*)(av_d + hh * 16 + (l & 3) * 4);
    float ss = hv.x * sa.x + hv.y * sa.y + hv.z * sa.z + hv.w * sa.w;
    float sd = hv.x * da.x + hv.y * da.y + hv.z * da.z + hv.w * da.w;
    ss += __shfl_xor_sync(0xffffffffu, ss, 1);
    ss += __shfl_xor_sync(0xffffffffu, ss, 2);
    sd += __shfl_xor_sync(0xffffffffu, sd, 1);
    sd += __shfl_xor_sync(0xffffffffu, sd, 2);
    if ((l & 3) == 0) { os[n * 8 + hh] = ss; od[n * 8 + hh] = sd; }
}

// ---------------- layer0 aggregation, fully fused softmax: block(128)/dst ----------------
__global__ void agg0_kernel(const int* __restrict__ row_ptr,
                            const int* __restrict__ csr_src,
                            const float* __restrict__ as,
                            const float* __restrict__ ad,
                            const float* __restrict__ h,
                            const float* __restrict__ b0,
                            float* __restrict__ out) {
    int dst = blockIdx.x;
    int idx = threadIdx.x;
    __shared__ float s_ad[8];
    __shared__ int s_src[128];
    __shared__ float s_al[128 * 8];
    if (idx < 8) s_ad[idx] = ad[dst * 8 + idx];
    __syncthreads();
    int s = row_ptr[dst], e = row_ptr[dst + 1];
    int hh = idx >> 4;
    float acc = 0.f, den = 0.f;
    for (int base = s; base < e; base += 128) {
        int n = min(128, e - base);
        if (idx < n) {
            int src = csr_src[base + idx];
            s_src[idx] = src;
            float4 s0 = ((const float4*)(as + src * 8))[0];
            float4 s1 = ((const float4*)(as + src * 8))[1];
            float v[8] = {s0.x + s_ad[0], s0.y + s_ad[1], s0.z + s_ad[2], s0.w + s_ad[3],
                          s1.x + s_ad[4], s1.y + s_ad[5], s1.z + s_ad[6], s1.w + s_ad[7]};
#pragma unroll
            for (int j = 0; j < 8; j++) {
                float t = v[j];
                t = t > 0.f ? t : 0.2f * t;
                v[j] = __expf(t);
            }
            ((float4*)(s_al + idx * 8))[0] = make_float4(v[0], v[1], v[2], v[3]);
            ((float4*)(s_al + idx * 8))[1] = make_float4(v[4], v[5], v[6], v[7]);
        }
        __syncthreads();
#pragma unroll 4
        for (int i = 0; i < n; i++) {
            float a = s_al[i * 8 + hh];
            den += a;
            acc += a * h[(size_t)s_src[i] * HID + idx];
        }
        __syncthreads();
    }
    float v = acc / (den + 1e-16f) + b0[idx];
    out[(size_t)dst * HID + idx] = v > 0.f ? v : expm1f(v);
}

// ---------------- fold W1 with attention vectors ----------------
__global__ void gemv_w1a_kernel(const float* __restrict__ W1,
                                const float* __restrict__ a_s,
                                const float* __restrict__ a_d,
                                float* __restrict__ avs, float* __restrict__ avd) {
    int o = blockIdx.x * blockDim.x + threadIdx.x;
    if (o >= HID * HEADS) return;
    int k = o >> 3, hh = o & 7;
    const float* wrow = W1 + (size_t)k * 512 + hh * 64;
    const float* sv = a_s + hh * 64;
    const float* dv = a_d + hh * 64;
    float ss = 0.f, sd = 0.f;
#pragma unroll 16
    for (int c = 0; c < 64; c++) {
        float w = wrow[c];
        ss += w * sv[c];
        sd += w * dv[c];
    }
    avs[k * 8 + hh] = ss;
    avd[k * 8 + hh] = sd;
}

// ---------------- alpha layer1: block(128) per 8 nodes ----------------
__global__ void alpha1_kernel(const float* __restrict__ agg0,
                              const float* __restrict__ avs,
                              const float* __restrict__ avd,
                              float* __restrict__ os, float* __restrict__ od) {
    __shared__ float s_a[8][HID + 1];
    __shared__ float s_t[HID][16];
    int tid = threadIdx.x;
    int n0 = blockIdx.x * 8;
#pragma unroll
    for (int i = tid; i < HID * 8; i += 128) {
        int k = i >> 3, hh = i & 7;
        s_t[k][hh] = avs[i];
        s_t[k][8 + hh] = avd[i];
    }
#pragma unroll
    for (int r = 0; r < 8; r++) {
        int n = n0 + r;
        float v = (n < N_NODES) ? agg0[(size_t)n * HID + tid] : 0.f;
        s_a[r][tid] = v;
    }
    __syncthreads();
    int node = tid >> 4;
    int outp = tid & 15;
    float acc = 0.f;
#pragma unroll 8
    for (int k = 0; k < HID; k++) acc += s_a[node][k] * s_t[k][outp];
    int n = n0 + node;
    if (n < N_NODES) {
        if (outp < 8) os[n * 8 + outp] = acc;
        else od[n * 8 + (outp - 8)] = acc;
    }
}

// ---------------- layer1 aggregation (z-trick), fully fused softmax: block(128)/dst ----------------
__global__ void aggz_kernel(const int* __restrict__ row_ptr,
                            const int* __restrict__ csr_src,
                            const float* __restrict__ as,
                            const float* __restrict__ ad,
                            const float* __restrict__ agg0,
                            float* __restrict__ z) {
    int dst = blockIdx.x;
    int idx = threadIdx.x;  // k dim 0..127
    __shared__ float s_ad[8];
    __shared__ int s_src[128];
    __shared__ float s_al[128 * 8];
    __shared__ float s_rden[8];
    if (idx < 8) s_ad[idx] = ad[dst * 8 + idx];
    __syncthreads();
    int s = row_ptr[dst], e = row_ptr[dst + 1];
    float acc[8];
#pragma unroll
    for (int hh = 0; hh < 8; hh++) acc[hh] = 0.f;
    float den_own = 0.f;
    int ownh = idx & 7;
    for (int base = s; base < e; base += 128) {
        int n = min(128, e - base);
        if (idx < n) {
            int src = csr_src[base + idx];
            s_src[idx] = src;
            float4 s0 = ((const float4*)(as + src * 8))[0];
            float4 s1 = ((const float4*)(as + src * 8))[1];
            float v[8] = {s0.x + s_ad[0], s0.y + s_ad[1], s0.z + s_ad[2], s0.w + s_ad[3],
                          s1.x + s_ad[4], s1.y + s_ad[5], s1.z + s_ad[6], s1.w + s_ad[7]};
#pragma unroll
            for (int j = 0; j < 8; j++) {
                float t = v[j];
                t = t > 0.f ? t : 0.2f * t;
                v[j] = __expf(t);
            }
            ((float4*)(s_al + idx * 8))[0] = make_float4(v[0], v[1], v[2], v[3]);
            ((float4*)(s_al + idx * 8))[1] = make_float4(v[4], v[5], v[6], v[7]);
        }
        __syncthreads();
#pragma unroll 2
        for (int i = 0; i < n; i++) {
            float v = agg0[(size_t)s_src[i] * HID + idx];
            den_own += s_al[i * 8 + ownh];
#pragma unroll
            for (int hh = 0; hh < 8; hh++) acc[hh] += s_al[i * 8 + hh] * v;
        }
        __syncthreads();
    }
    if (idx < 8) s_rden[idx] = 0.f;
    __syncthreads();
    if (idx < 8) s_rden[idx] = 0.125f / (den_own + 1e-16f);
    __syncthreads();
#pragma unroll
    for (int hh = 0; hh < 8; hh++)
        z[(size_t)dst * 1024 + hh * HID + idx] = acc[hh] * s_rden[hh];
}

// ---------------- stack W1: W1s[(h*128+k)][c] = W1[k][h*64+c] ----------------
__global__ void permW1s_kernel(const float* __restrict__ W1, float* __restrict__ W1s) {
    int i = blockIdx.x * blockDim.x + threadIdx.x;
    if (i >= HID * 512) return;
    int k = i >> 9;
    int j = i & 511;
    int hh = j >> 6, c = j & 63;
    W1s[(size_t)(hh * HID + k) * NCLS + c] = W1[i];
}

// ---------------- finalize: log_softmax(zout + b1); warp per node ----------------
__global__ void finalize_kernel(const float* __restrict__ zo,
                                const float* __restrict__ b1,
                                float* __restrict__ out) {
    int t = blockIdx.x * blockDim.x + threadIdx.x;
    int n = t >> 5, lane = t & 31;
    if (n >= N_NODES) return;
    float v0 = zo[(size_t)n * NCLS + lane] + b1[lane];
    float v1 = zo[(size_t)n * NCLS + lane + 32] + b1[lane + 32];
    float mx = fmaxf(v0, v1);
#pragma unroll
    for (int o = 16; o; o >>= 1) mx = fmaxf(mx, __shfl_xor_sync(0xffffffffu, mx, o));
    float s = expf(v0 - mx) + expf(v1 - mx);
#pragma unroll
    for (int o = 16; o; o >>= 1) s += __shfl_xor_sync(0xffffffffu, s, o);
    float lse = mx + logf(s);
    out[(size_t)n * NCLS + lane] = v0 - lse;
    out[(size_t)n * NCLS + lane + 32] = v1 - lse;
}

// ---------------- launch ----------------
extern "C" void kernel_launch(void* const* d_in, const int* in_sizes, int n_in,
                              void* d_out, int out_size) {
    const float* x   = (const float*)d_in[0];
    const void*  ei  = d_in[1];
    const float* W0  = (const float*)d_in[2];
    const float* as0 = (const float*)d_in[3];
    const float* ad0 = (const float*)d_in[4];
    const float* b0  = (const float*)d_in[5];
    const float* W1  = (const float*)d_in[6];
    const float* as1 = (const float*)d_in[7];
    const float* ad1 = (const float*)d_in[8];
    const float* b1  = (const float*)d_in[9];
    float* out = (float*)d_out;

    float *h0, *z, *as, *ad, *agg0, *W1s, *avs, *avd, *zout;
    int *deg, *cur, *rowptr, *csrs, *csrd, *bsum, *boff;
    cudaGetSymbolAddress((void**)&h0,    g_h0);
    cudaGetSymbolAddress((void**)&z,     g_z);
    cudaGetSymbolAddress((void**)&as,    g_as);
    cudaGetSymbolAddress((void**)&ad,    g_ad);
    cudaGetSymbolAddress((void**)&agg0,  g_agg0);
    cudaGetSymbolAddress((void**)&W1s,   g_W1s);
    cudaGetSymbolAddress((void**)&avs,   g_avs);
    cudaGetSymbolAddress((void**)&avd,   g_avd);
    cudaGetSymbolAddress((void**)&zout,  g_zout);
    cudaGetSymbolAddress((void**)&deg,   g_deg);
    cudaGetSymbolAddress((void**)&cur,   g_cur);
    cudaGetSymbolAddress((void**)&rowptr,g_rowptr);
    cudaGetSymbolAddress((void**)&csrs,  g_csr_src);
    cudaGetSymbolAddress((void**)&csrd,  g_csr_dst);
    cudaGetSymbolAddress((void**)&bsum,  g_bsum);
    cudaGetSymbolAddress((void**)&boff,  g_boff);

    const int TB = 256;
    const int EBLK = (N_EDGES + TB - 1) / TB;
    const int NBLK = (N_NODES + TB - 1) / TB;
    const int WBLK = (N_NODES * 32 + TB - 1) / TB;

    // launches 0-2
    init_kernel<<<NBLK, TB>>>(deg, cur, (const int*)ei);
    hist_kernel<<<EBLK, TB>>>(ei, deg);
    scanA_kernel<<<SCAN_G, SCAN_B>>>(deg, bsum);
    // launch 3: layer0 GEMM (profiled)
    sgemm2_kernel<128, 8><<<dim3(1, (N_NODES + 127) / 128), 256>>>(
        N_NODES, HID, 256, x, W0, h0);
    // CSR completion
    scanB_kernel<<<1, 256>>>(bsum, boff);
    scanC_kernel<<<SCAN_G, SCAN_B>>>(deg, boff, rowptr);
    fill_kernel<<<EBLK, TB>>>(ei, rowptr, cur, csrs, csrd);

    // layer 0
    alpha0_kernel<<<WBLK, TB>>>(h0, as0, ad0, as, ad);
    agg0_kernel<<<N_NODES, 128>>>(rowptr, csrs, as, ad, h0, b0, agg0);

    // layer 1
    gemv_w1a_kernel<<<(HID * HEADS + TB - 1) / TB, TB>>>(W1, as1, ad1, avs, avd);
    alpha1_kernel<<<(N_NODES + 7) / 8, 128>>>(agg0, avs, avd, as, ad);
    aggz_kernel<<<N_NODES, 128>>>(rowptr, csrs, as, ad, agg0, z);
    permW1s_kernel<<<(HID * 512 + TB - 1) / TB, TB>>>(W1, W1s);
    sgemm2_kernel<64, 4><<<dim3(1, (N_NODES + 127) / 128), 256>>>(
        N_NODES, NCLS, 1024, z, W1s, zout);
    finalize_kernel<<<WBLK, TB>>>(zout, b1, out);
}